// round 10
// baseline (speedup 1.0000x reference)
#include <cuda_runtime.h>
#include <cuda_bf16.h>
#include <cstdint>
#include <cstddef>

// Problem constants
#define BATCH 4096
#define NTOK 64
#define CDIM 192
#define NHEAD 6
#define HDIM 32
#define MROWS (BATCH * NTOK)   // 262144
#define QKVW 768               // q(192) + k(192) + v(192) + v_r(192)
#define KDIM 192

// ---------------------------------------------------------------------------
// Device scratch (no allocations allowed)
// ---------------------------------------------------------------------------
__device__ float g_qkv[(size_t)MROWS * QKVW];          // 805 MB
__device__ float g_att[(size_t)MROWS * CDIM];          // 201 MB
__device__ __nv_bfloat16 g_wh[768 * 192];              // qkv weights (N-major) hi
__device__ __nv_bfloat16 g_wl[768 * 192];
__device__ __nv_bfloat16 g_pwh[192 * 192];
__device__ __nv_bfloat16 g_pwl[192 * 192];
__device__ float g_bias[768];                          // concat(bq, bkv)
__device__ float g_bmat[NHEAD * NTOK * NTOK];          // precomputed rel-pos bias

// ---------------------------------------------------------------------------
// MMA helpers (portable on compute_103: ldmatrix + mma.sync are sm_80 features)
// ---------------------------------------------------------------------------
__device__ __forceinline__ uint32_t smem_u32(const void* p) {
    uint32_t a;
    asm("{ .reg .u64 t; cvta.to.shared.u64 t, %1; cvt.u32.u64 %0, t; }"
        : "=r"(a) : "l"(p));
    return a;
}

__device__ __forceinline__ void ldsm4(uint32_t addr, uint32_t r[4]) {
    asm volatile("ldmatrix.sync.aligned.m8n8.x4.shared.b16 {%0,%1,%2,%3}, [%4];"
        : "=r"(r[0]), "=r"(r[1]), "=r"(r[2]), "=r"(r[3]) : "r"(addr));
}

__device__ __forceinline__ void mma16816(float c[4], const uint32_t a[4],
                                         uint32_t b0, uint32_t b1) {
    asm volatile(
        "mma.sync.aligned.m16n8k16.row.col.f32.bf16.bf16.f32 "
        "{%0,%1,%2,%3}, {%4,%5,%6,%7}, {%8,%9}, {%0,%1,%2,%3};"
        : "+f"(c[0]), "+f"(c[1]), "+f"(c[2]), "+f"(c[3])
        : "r"(a[0]), "r"(a[1]), "r"(a[2]), "r"(a[3]), "r"(b0), "r"(b1));
}

__device__ __forceinline__ uint32_t packbf2(float a, float b) {
    __nv_bfloat162 t = __floats2bfloat162_rn(a, b);   // .x = a (low), .y = b
    return *(uint32_t*)&t;
}

__device__ __forceinline__ void bf16_split(float v, __nv_bfloat16& h, __nv_bfloat16& l) {
    h = __float2bfloat16(v);
    l = __float2bfloat16(v - __bfloat162float(h));
}

// Split float4 -> packed hi (2x u32) and lo (2x u32)
__device__ __forceinline__ void split4(const float4 v, uint32_t hi[2], uint32_t lo[2]) {
    __nv_bfloat16 h0, l0, h1, l1;
    bf16_split(v.x, h0, l0); bf16_split(v.y, h1, l1);
    hi[0] = ((uint32_t)*(uint16_t*)&h1 << 16) | *(uint16_t*)&h0;
    lo[0] = ((uint32_t)*(uint16_t*)&l1 << 16) | *(uint16_t*)&l0;
    bf16_split(v.z, h0, l0); bf16_split(v.w, h1, l1);
    hi[1] = ((uint32_t)*(uint16_t*)&h1 << 16) | *(uint16_t*)&h0;
    lo[1] = ((uint32_t)*(uint16_t*)&l1 << 16) | *(uint16_t*)&l0;
}

// Weights: transpose to N-major [n][k] and split; concat biases; bias matrices.
__global__ __launch_bounds__(256) void prep_w_kernel(
    const float* __restrict__ wq, const float* __restrict__ wkv,
    const float* __restrict__ bq, const float* __restrict__ bkv,
    const float* __restrict__ projw,
    const float* __restrict__ rpb, const int* __restrict__ relidx)
{
    int idx = blockIdx.x * 256 + threadIdx.x;
    if (idx < 768 * 192) {
        int n = idx / 192, k = idx % 192;
        float v = (n < 192) ? wq[k * 192 + n] : wkv[k * 576 + (n - 192)];
        bf16_split(v, g_wh[idx], g_wl[idx]);
    } else if (idx < 768 * 192 + 192 * 192) {
        int j = idx - 768 * 192;
        int n = j / 192, k = j % 192;
        bf16_split(projw[k * 192 + n], g_pwh[j], g_pwl[j]);
    }
    if (idx < 768) g_bias[idx] = (idx < 192) ? bq[idx] : bkv[idx - 192];
    if (idx < NTOK * NTOK) {
        int ri = relidx[idx];
#pragma unroll
        for (int h = 0; h < NHEAD; h++)
            g_bmat[h * (NTOK * NTOK) + idx] = rpb[ri * NHEAD + h];
    }
}

// ---------------------------------------------------------------------------
// HMMA GEMM: C[64x64 tile] = A_fp32[64xK] @ (Bh+Bl)^T[Kx64] + bias
// A is fp32, split to bf16 hi/lo IN the load phase (no global split pass).
// 3-pass split: Ah*Bh + Al*Bh + Ah*Bl, fp32 accum. K=192 resident in SMEM.
// ---------------------------------------------------------------------------
#define LDSG 200
#define SM_AH 0
#define SM_AL (64 * LDSG)
#define SM_BH (128 * LDSG)
#define SM_BL (192 * LDSG)
#define GEMM_SMEM (256 * LDSG * 2)     // 102400 bytes

__global__ __launch_bounds__(128) void gemm_tc_kernel(
    const float* __restrict__ A,
    const __nv_bfloat16* __restrict__ Bh, const __nv_bfloat16* __restrict__ Bl,
    const float* __restrict__ bias, float* __restrict__ C, int ldc)
{
    extern __shared__ __nv_bfloat16 sm[];
    const int t = threadIdx.x;
    const int lane = t & 31;
    const int wid = t >> 5;
    const int wm = wid >> 1;
    const int wn = wid & 1;
    const int n0   = blockIdx.x * 64;
    const int row0 = blockIdx.y * 64;

    // Load A tile (64x192 fp32), split to hi/lo in registers, STS packed
#pragma unroll
    for (int it = 0; it < 24; it++) {
        int idx = it * 128 + t;
        int r = idx / 48;
        int k = (idx % 48) * 4;
        float4 a = *(const float4*)(A + (size_t)(row0 + r) * KDIM + k);
        uint32_t hi[2], lo[2];
        split4(a, hi, lo);
        int s = r * LDSG + k;
        *(uint32_t*)(sm + SM_AH + s)     = hi[0];
        *(uint32_t*)(sm + SM_AH + s + 2) = hi[1];
        *(uint32_t*)(sm + SM_AL + s)     = lo[0];
        *(uint32_t*)(sm + SM_AL + s + 2) = lo[1];
    }
    // Load B tile (64 n-rows x 192, hi+lo, already bf16)
#pragma unroll
    for (int it = 0; it < 24; it++) {
        int idx = it * 128 + t;
        int r = idx / 48;
        int k = (idx % 48) * 4;
        size_t g = (size_t)(n0 + r) * KDIM + k;
        int s = r * LDSG + k;
        *(uint64_t*)(sm + SM_BH + s) = *(const uint64_t*)(Bh + g);
        *(uint64_t*)(sm + SM_BL + s) = *(const uint64_t*)(Bl + g);
    }
    __syncthreads();

    float acc[2][4][4];
#pragma unroll
    for (int i = 0; i < 2; i++)
#pragma unroll
        for (int j = 0; j < 4; j++)
#pragma unroll
            for (int e = 0; e < 4; e++) acc[i][j][e] = 0.0f;

    const uint32_t sbase = smem_u32(sm);
    const uint32_t aoff = (uint32_t)((wm * 32 + (lane & 15)) * LDSG + ((lane >> 4) << 3));
    const uint32_t boff = (uint32_t)((wn * 32 + (lane & 7) + ((lane >> 4) << 3)) * LDSG
                                     + (((lane >> 3) & 1) << 3));

#pragma unroll
    for (int pass = 0; pass < 3; pass++) {
        const uint32_t aBase = sbase + 2u * (pass == 1 ? SM_AL : SM_AH);
        const uint32_t bBase = sbase + 2u * (pass == 2 ? SM_BL : SM_BH);
#pragma unroll
        for (int ks = 0; ks < 12; ks++) {
            const uint32_t k0 = ks * 16;
            uint32_t a0[4], a1[4], b0[4], b1[4];
            ldsm4(aBase + (aoff + k0) * 2, a0);
            ldsm4(aBase + (aoff + 16 * LDSG + k0) * 2, a1);
            ldsm4(bBase + (boff + k0) * 2, b0);
            ldsm4(bBase + (boff + 16 * LDSG + k0) * 2, b1);

            mma16816(acc[0][0], a0, b0[0], b0[1]);
            mma16816(acc[0][1], a0, b0[2], b0[3]);
            mma16816(acc[0][2], a0, b1[0], b1[1]);
            mma16816(acc[0][3], a0, b1[2], b1[3]);
            mma16816(acc[1][0], a1, b0[0], b0[1]);
            mma16816(acc[1][1], a1, b0[2], b0[3]);
            mma16816(acc[1][2], a1, b1[0], b1[1]);
            mma16816(acc[1][3], a1, b1[2], b1[3]);
        }
    }

    const int r_base = row0 + wm * 32 + (lane >> 2);
    const int c_base = n0 + wn * 32 + (lane & 3) * 2;
#pragma unroll
    for (int nt = 0; nt < 4; nt++) {
        const int col = c_base + nt * 8;
        const float bv0 = bias[col];
        const float bv1 = bias[col + 1];
#pragma unroll
        for (int mt = 0; mt < 2; mt++) {
            const int r = r_base + mt * 16;
            float2 v0 = make_float2(acc[mt][nt][0] + bv0, acc[mt][nt][1] + bv1);
            float2 v1 = make_float2(acc[mt][nt][2] + bv0, acc[mt][nt][3] + bv1);
            *(float2*)(C + (size_t)r * ldc + col)       = v0;
            *(float2*)(C + (size_t)(r + 8) * ldc + col) = v1;
        }
    }
}

// ---------------------------------------------------------------------------
// HMMA attention: one block per (batch, head), 128 threads = 4 warps.
// q/k STS vectorized (bf16x2); V stored transposed (scalar, 2-way max confl).
// ---------------------------------------------------------------------------
__global__ __launch_bounds__(128) void attn_kernel(
    const float* __restrict__ qkv, const float* __restrict__ bmat,
    float* __restrict__ out)
{
    const int h = blockIdx.x % NHEAD;
    const int b = blockIdx.x / NHEAD;
    const int t = threadIdx.x;
    const int lane = t & 31;
    const int w = t >> 5;

    __shared__ __nv_bfloat16 qh[64][40], ql[64][40];
    __shared__ __nv_bfloat16 kh[64][40], kl[64][40];
    __shared__ __nv_bfloat16 vth[32][72], vtl[32][72];  // [d][token]

    // ---- load + split ----
    {
        const int n = t >> 1;
        const int half = t & 1;
        const float scale = 0.1767766952966369f;  // 1/sqrt(32)
        const float* base = qkv + (size_t)(b * 64 + n) * QKVW + h * HDIM + half * 16;
#pragma unroll
        for (int i = 0; i < 4; i++) {
            float4 qv = *(const float4*)(base + i * 4);
            float4 kv = *(const float4*)(base + 192 + i * 4);
            float4 vv = *(const float4*)(base + 384 + i * 4);
            qv.x *= scale; qv.y *= scale; qv.z *= scale; qv.w *= scale;
            const int c0 = half * 16 + i * 4;
            uint32_t hi[2], lo[2];
            split4(qv, hi, lo);
            *(uint32_t*)&qh[n][c0]     = hi[0];
            *(uint32_t*)&qh[n][c0 + 2] = hi[1];
            *(uint32_t*)&ql[n][c0]     = lo[0];
            *(uint32_t*)&ql[n][c0 + 2] = lo[1];
            split4(kv, hi, lo);
            *(uint32_t*)&kh[n][c0]     = hi[0];
            *(uint32_t*)&kh[n][c0 + 2] = hi[1];
            *(uint32_t*)&kl[n][c0]     = lo[0];
            *(uint32_t*)&kl[n][c0 + 2] = lo[1];
            const float vf[4] = {vv.x, vv.y, vv.z, vv.w};
#pragma unroll
            for (int e = 0; e < 4; e++) {
                __nv_bfloat16 hh, ll;
                bf16_split(vf[e], hh, ll);
                vth[c0 + e][n] = hh; vtl[c0 + e][n] = ll;
            }
        }
    }
    __syncthreads();

    // ---- QK^T ----
    float s[8][4];
#pragma unroll
    for (int j = 0; j < 8; j++)
#pragma unroll
        for (int e = 0; e < 4; e++) s[j][e] = 0.0f;

    const uint32_t qhB = smem_u32(&qh[0][0]);
    const uint32_t qlB = smem_u32(&ql[0][0]);
    const uint32_t khB = smem_u32(&kh[0][0]);
    const uint32_t klB = smem_u32(&kl[0][0]);
    const uint32_t aoff = (uint32_t)((16 * w + (lane & 15)) * 40 + ((lane >> 4) << 3));
    const uint32_t boff = (uint32_t)(((lane & 7) + ((lane >> 4) << 3)) * 40
                                     + (((lane >> 3) & 1) << 3));

#pragma unroll
    for (int pass = 0; pass < 3; pass++) {
        const uint32_t aB = (pass == 1) ? qlB : qhB;
        const uint32_t bB = (pass == 2) ? klB : khB;
#pragma unroll
        for (int ks = 0; ks < 2; ks++) {
            uint32_t A[4];
            ldsm4(aB + (aoff + ks * 16) * 2, A);
#pragma unroll
            for (int nt = 0; nt < 4; nt++) {
                uint32_t B[4];
                ldsm4(bB + (boff + nt * 16 * 40 + ks * 16) * 2, B);
                mma16816(s[2 * nt],     A, B[0], B[1]);
                mma16816(s[2 * nt + 1], A, B[2], B[3]);
            }
        }
    }

    // ---- bias + softmax (rows r0 = 16w + lane/4, r1 = r0+8) ----
    const int r0 = 16 * w + (lane >> 2);
    const int cb = 2 * (lane & 3);
    const float* bm = bmat + h * 4096;
#pragma unroll
    for (int j = 0; j < 8; j++) {
        float2 b0 = *(const float2*)(bm + r0 * 64 + 8 * j + cb);
        float2 b1 = *(const float2*)(bm + (r0 + 8) * 64 + 8 * j + cb);
        s[j][0] += b0.x; s[j][1] += b0.y;
        s[j][2] += b1.x; s[j][3] += b1.y;
    }

    float mx0 = -1e30f, mx1 = -1e30f;
#pragma unroll
    for (int j = 0; j < 8; j++) {
        mx0 = fmaxf(mx0, fmaxf(s[j][0], s[j][1]));
        mx1 = fmaxf(mx1, fmaxf(s[j][2], s[j][3]));
    }
    mx0 = fmaxf(mx0, __shfl_xor_sync(0xffffffffu, mx0, 1));
    mx0 = fmaxf(mx0, __shfl_xor_sync(0xffffffffu, mx0, 2));
    mx1 = fmaxf(mx1, __shfl_xor_sync(0xffffffffu, mx1, 1));
    mx1 = fmaxf(mx1, __shfl_xor_sync(0xffffffffu, mx1, 2));

    float sum0 = 0.0f, sum1 = 0.0f;
#pragma unroll
    for (int j = 0; j < 8; j++) {
        s[j][0] = __expf(s[j][0] - mx0); sum0 += s[j][0];
        s[j][1] = __expf(s[j][1] - mx0); sum0 += s[j][1];
        s[j][2] = __expf(s[j][2] - mx1); sum1 += s[j][2];
        s[j][3] = __expf(s[j][3] - mx1); sum1 += s[j][3];
    }
    sum0 += __shfl_xor_sync(0xffffffffu, sum0, 1);
    sum0 += __shfl_xor_sync(0xffffffffu, sum0, 2);
    sum1 += __shfl_xor_sync(0xffffffffu, sum1, 1);
    sum1 += __shfl_xor_sync(0xffffffffu, sum1, 2);
    const float inv0 = 1.0f / sum0;
    const float inv1 = 1.0f / sum1;

    // ---- P -> bf16 hi/lo A-fragments in registers ----
    uint32_t ph[4][4], pl[4][4];
#pragma unroll
    for (int ks = 0; ks < 4; ks++) {
        const int j0 = 2 * ks, j1 = 2 * ks + 1;
        float p[8] = { s[j0][0] * inv0, s[j0][1] * inv0,
                       s[j0][2] * inv1, s[j0][3] * inv1,
                       s[j1][0] * inv0, s[j1][1] * inv0,
                       s[j1][2] * inv1, s[j1][3] * inv1 };
        float hi[8], lo[8];
#pragma unroll
        for (int e = 0; e < 8; e++) {
            __nv_bfloat16 hh = __float2bfloat16(p[e]);
            hi[e] = __bfloat162float(hh);
            lo[e] = p[e] - hi[e];
        }
        ph[ks][0] = packbf2(hi[0], hi[1]); pl[ks][0] = packbf2(lo[0], lo[1]);
        ph[ks][1] = packbf2(hi[2], hi[3]); pl[ks][1] = packbf2(lo[2], lo[3]);
        ph[ks][2] = packbf2(hi[4], hi[5]); pl[ks][2] = packbf2(lo[4], lo[5]);
        ph[ks][3] = packbf2(hi[6], hi[7]); pl[ks][3] = packbf2(lo[6], lo[7]);
    }

    // ---- PV ----
    float o[4][4];
#pragma unroll
    for (int j = 0; j < 4; j++)
#pragma unroll
        for (int e = 0; e < 4; e++) o[j][e] = 0.0f;

    const uint32_t vhB = smem_u32(&vth[0][0]);
    const uint32_t vlB = smem_u32(&vtl[0][0]);
    const uint32_t vrow = (uint32_t)((lane & 7) + ((lane >> 4) << 3));
    const uint32_t vcol = (uint32_t)(((lane >> 3) & 1) << 3);

#pragma unroll
    for (int pass = 0; pass < 3; pass++) {
        const uint32_t (*A)[4] = (pass == 1) ? pl : ph;
        const uint32_t vB = (pass == 2) ? vlB : vhB;
#pragma unroll
        for (int ks = 0; ks < 4; ks++) {
            uint32_t B0[4], B1[4];
            ldsm4(vB + ((vrow) * 72 + ks * 16 + vcol) * 2, B0);
            ldsm4(vB + ((vrow + 16) * 72 + ks * 16 + vcol) * 2, B1);
            mma16816(o[0], A[ks], B0[0], B0[1]);
            mma16816(o[1], A[ks], B0[2], B0[3]);
            mma16816(o[2], A[ks], B1[0], B1[1]);
            mma16816(o[3], A[ks], B1[2], B1[3]);
        }
    }

    // ---- store ----
    float* op = out + (size_t)(b * 64) * CDIM + h * HDIM;
#pragma unroll
    for (int j = 0; j < 4; j++) {
        const int d = 8 * j + cb;
        *(float2*)(op + (size_t)r0 * CDIM + d)       = make_float2(o[j][0], o[j][1]);
        *(float2*)(op + (size_t)(r0 + 8) * CDIM + d) = make_float2(o[j][2], o[j][3]);
    }
}

// ---------------------------------------------------------------------------
// Positional conv branch (validated in R6, unchanged)
// ---------------------------------------------------------------------------
#define CONV_SMEM ((64 * 192 + 64 * 192 + 32 * 193) * 4)

__global__ __launch_bounds__(192) void conv_kernel(
    const float* __restrict__ qkv, const float* __restrict__ dw_w,
    const float* __restrict__ dw_b, const float* __restrict__ pw_w,
    const float* __restrict__ pw_b, float* __restrict__ att)
{
    extern __shared__ float smf[];
    float* vt   = smf;
    float* pt   = smf + 64 * 192;
    float* pw_s = smf + 2 * 64 * 192;

    const int b = blockIdx.x;
    const int c = threadIdx.x;

    const float* src = qkv + (size_t)b * 64 * QKVW + 576;
#pragma unroll
    for (int p = 0; p < 64; p++)
        vt[p * 192 + c] = src[(size_t)p * QKVW + c];

#pragma unroll
    for (int i = 0; i < 32; i++) {
        int idx = i * 192 + c;
        int cc = idx >> 5, d = idx & 31;
        pw_s[d * 193 + cc] = pw_w[idx];
    }
    __syncthreads();

    float in[64];
#pragma unroll
    for (int p = 0; p < 64; p++) in[p] = vt[p * 192 + c];

    float w[25];
#pragma unroll
    for (int i = 0; i < 25; i++) w[i] = dw_w[c * 25 + i];
    const float db = dw_b[c];

#pragma unroll
    for (int p = 0; p < 64; p++) {
        const int y = p >> 3, x = p & 7;
        float a = db;
#pragma unroll
        for (int ky = 0; ky < 5; ky++) {
            const int yy = y + ky - 2;
            if (yy < 0 || yy > 7) continue;
#pragma unroll
            for (int kx = 0; kx < 5; kx++) {
                const int xx = x + kx - 2;
                if (xx < 0 || xx > 7) continue;
                a += in[yy * 8 + xx] * w[ky * 5 + kx];
            }
        }
        pt[p * 192 + c] = a;
    }
    __syncthreads();

    float wv[32];
#pragma unroll
    for (int d = 0; d < 32; d++) wv[d] = pw_s[d * 193 + c];
    const float pb = pw_b[c];
    const int g32 = (c >> 5) << 5;

    float* dst = att + (size_t)b * 64 * CDIM;
#pragma unroll
    for (int p = 0; p < 64; p++) {
        const float4* pr = (const float4*)(pt + p * 192 + g32);
        float a = pb;
#pragma unroll
        for (int d4 = 0; d4 < 8; d4++) {
            float4 v = pr[d4];
            a += v.x * wv[d4 * 4 + 0] + v.y * wv[d4 * 4 + 1]
               + v.z * wv[d4 * 4 + 2] + v.w * wv[d4 * 4 + 3];
        }
        dst[p * 192 + c] += a;
    }
}

// ---------------------------------------------------------------------------
extern "C" void kernel_launch(void* const* d_in, const int* in_sizes, int n_in,
                              void* d_out, int out_size)
{
    const float* x      = (const float*)d_in[0];
    const float* wq     = (const float*)d_in[1];
    const float* bq     = (const float*)d_in[2];
    const float* wkv    = (const float*)d_in[3];
    const float* bkv    = (const float*)d_in[4];
    const float* rpb    = (const float*)d_in[5];
    const int*   relidx = (const int*)  d_in[6];
    const float* dw_w   = (const float*)d_in[7];
    const float* dw_b   = (const float*)d_in[8];
    const float* pw_w   = (const float*)d_in[9];
    const float* pw_b   = (const float*)d_in[10];
    const float* proj_w = (const float*)d_in[11];
    const float* proj_b = (const float*)d_in[12];
    float* out = (float*)d_out;

    float *qkv, *att, *biasc, *bmat;
    __nv_bfloat16 *wh, *wl, *pwh, *pwl;
    cudaGetSymbolAddress((void**)&qkv,  g_qkv);
    cudaGetSymbolAddress((void**)&att,  g_att);
    cudaGetSymbolAddress((void**)&wh,   g_wh);
    cudaGetSymbolAddress((void**)&wl,   g_wl);
    cudaGetSymbolAddress((void**)&pwh,  g_pwh);
    cudaGetSymbolAddress((void**)&pwl,  g_pwl);
    cudaGetSymbolAddress((void**)&biasc, g_bias);
    cudaGetSymbolAddress((void**)&bmat, g_bmat);

    cudaFuncSetAttribute(gemm_tc_kernel,
                         cudaFuncAttributeMaxDynamicSharedMemorySize, GEMM_SMEM);
    cudaFuncSetAttribute(conv_kernel,
                         cudaFuncAttributeMaxDynamicSharedMemorySize, CONV_SMEM);

    // 0) weight prep (incl. bias matrices)
    prep_w_kernel<<<(768 * 192 + 192 * 192 + 255) / 256, 256>>>(
        wq, wkv, bq, bkv, proj_w, rpb, relidx);

    // 1) fused q|k|v|v_r GEMM (fp32 A, split in-kernel) -> g_qkv
    gemm_tc_kernel<<<dim3(QKVW / 64, MROWS / 64), 128, GEMM_SMEM>>>(
        x, wh, wl, biasc, qkv, QKVW);

    // 2) attention -> g_att (HMMA)
    attn_kernel<<<BATCH * NHEAD, 128>>>(qkv, bmat, att);

    // 3) conv branch accumulates into g_att
    conv_kernel<<<BATCH, 192, CONV_SMEM>>>(qkv, dw_w, dw_b, pw_w, pw_b, att);

    // 4) proj GEMM (fp32 A, split in-kernel) -> d_out
    gemm_tc_kernel<<<dim3(CDIM / 64, MROWS / 64), 128, GEMM_SMEM>>>(
        att, pwh, pwl, proj_b, out, CDIM);
}

// round 11
// speedup vs baseline: 1.0811x; 1.0811x over previous
#include <cuda_runtime.h>
#include <cuda_bf16.h>
#include <cstdint>
#include <cstddef>

// Problem constants
#define BATCH 4096
#define NTOK 64
#define CDIM 192
#define NHEAD 6
#define HDIM 32
#define MROWS (BATCH * NTOK)   // 262144
#define QKVW 768               // q(192) + k(192) + v(192) + v_r(192)
#define KDIM 192

// ---------------------------------------------------------------------------
// Device scratch (no allocations allowed)
// ---------------------------------------------------------------------------
__device__ float g_qkv[(size_t)MROWS * QKVW];          // 805 MB
__device__ float g_att[(size_t)MROWS * CDIM];          // 201 MB
__device__ __nv_bfloat16 g_wh[768 * 192];              // qkv weights (N-major) hi
__device__ __nv_bfloat16 g_wl[768 * 192];
__device__ __nv_bfloat16 g_pwh[192 * 192];
__device__ __nv_bfloat16 g_pwl[192 * 192];
__device__ float g_bias[768];                          // concat(bq, bkv)
__device__ float g_bmat[NHEAD * NTOK * NTOK];          // precomputed rel-pos bias

// ---------------------------------------------------------------------------
// MMA helpers (portable on compute_103: ldmatrix + mma.sync are sm_80 features)
// ---------------------------------------------------------------------------
__device__ __forceinline__ uint32_t smem_u32(const void* p) {
    uint32_t a;
    asm("{ .reg .u64 t; cvta.to.shared.u64 t, %1; cvt.u32.u64 %0, t; }"
        : "=r"(a) : "l"(p));
    return a;
}

__device__ __forceinline__ void ldsm4(uint32_t addr, uint32_t r[4]) {
    asm volatile("ldmatrix.sync.aligned.m8n8.x4.shared.b16 {%0,%1,%2,%3}, [%4];"
        : "=r"(r[0]), "=r"(r[1]), "=r"(r[2]), "=r"(r[3]) : "r"(addr));
}

__device__ __forceinline__ void ldsm4t(uint32_t addr, uint32_t r[4]) {
    asm volatile("ldmatrix.sync.aligned.m8n8.x4.trans.shared.b16 {%0,%1,%2,%3}, [%4];"
        : "=r"(r[0]), "=r"(r[1]), "=r"(r[2]), "=r"(r[3]) : "r"(addr));
}

__device__ __forceinline__ void mma16816(float c[4], const uint32_t a[4],
                                         uint32_t b0, uint32_t b1) {
    asm volatile(
        "mma.sync.aligned.m16n8k16.row.col.f32.bf16.bf16.f32 "
        "{%0,%1,%2,%3}, {%4,%5,%6,%7}, {%8,%9}, {%0,%1,%2,%3};"
        : "+f"(c[0]), "+f"(c[1]), "+f"(c[2]), "+f"(c[3])
        : "r"(a[0]), "r"(a[1]), "r"(a[2]), "r"(a[3]), "r"(b0), "r"(b1));
}

__device__ __forceinline__ uint32_t packbf2(float a, float b) {
    __nv_bfloat162 t = __floats2bfloat162_rn(a, b);   // .x = a (low), .y = b
    return *(uint32_t*)&t;
}

__device__ __forceinline__ void bf16_split(float v, __nv_bfloat16& h, __nv_bfloat16& l) {
    h = __float2bfloat16(v);
    l = __float2bfloat16(v - __bfloat162float(h));
}

// Split float4 -> packed hi (u64) and lo (u64), 4 bf16 each
__device__ __forceinline__ void split4_64(const float4 v, uint64_t& hi64, uint64_t& lo64) {
    __nv_bfloat16 h0, l0, h1, l1;
    uint32_t hi[2], lo[2];
    bf16_split(v.x, h0, l0); bf16_split(v.y, h1, l1);
    hi[0] = ((uint32_t)*(uint16_t*)&h1 << 16) | *(uint16_t*)&h0;
    lo[0] = ((uint32_t)*(uint16_t*)&l1 << 16) | *(uint16_t*)&l0;
    bf16_split(v.z, h0, l0); bf16_split(v.w, h1, l1);
    hi[1] = ((uint32_t)*(uint16_t*)&h1 << 16) | *(uint16_t*)&h0;
    lo[1] = ((uint32_t)*(uint16_t*)&l1 << 16) | *(uint16_t*)&l0;
    hi64 = ((uint64_t)hi[1] << 32) | hi[0];
    lo64 = ((uint64_t)lo[1] << 32) | lo[0];
}

// Weights: transpose to N-major [n][k] and split; concat biases; bias matrices.
__global__ __launch_bounds__(256) void prep_w_kernel(
    const float* __restrict__ wq, const float* __restrict__ wkv,
    const float* __restrict__ bq, const float* __restrict__ bkv,
    const float* __restrict__ projw,
    const float* __restrict__ rpb, const int* __restrict__ relidx)
{
    int idx = blockIdx.x * 256 + threadIdx.x;
    if (idx < 768 * 192) {
        int n = idx / 192, k = idx % 192;
        float v = (n < 192) ? wq[k * 192 + n] : wkv[k * 576 + (n - 192)];
        bf16_split(v, g_wh[idx], g_wl[idx]);
    } else if (idx < 768 * 192 + 192 * 192) {
        int j = idx - 768 * 192;
        int n = j / 192, k = j % 192;
        bf16_split(projw[k * 192 + n], g_pwh[j], g_pwl[j]);
    }
    if (idx < 768) g_bias[idx] = (idx < 192) ? bq[idx] : bkv[idx - 192];
    if (idx < NTOK * NTOK) {
        int ri = relidx[idx];
#pragma unroll
        for (int h = 0; h < NHEAD; h++)
            g_bmat[h * (NTOK * NTOK) + idx] = rpb[ri * NHEAD + h];
    }
}

// ---------------------------------------------------------------------------
// HMMA GEMM: C[64x64 tile] = A_fp32[64xK] @ (Bh+Bl)^T[Kx64] + bias
// A split to bf16 hi/lo in load phase (u64-packed STS). K=192 SMEM-resident.
// ---------------------------------------------------------------------------
#define LDSG 200
#define SM_AH 0
#define SM_AL (64 * LDSG)
#define SM_BH (128 * LDSG)
#define SM_BL (192 * LDSG)
#define GEMM_SMEM (256 * LDSG * 2)     // 102400 bytes

__global__ __launch_bounds__(128) void gemm_tc_kernel(
    const float* __restrict__ A,
    const __nv_bfloat16* __restrict__ Bh, const __nv_bfloat16* __restrict__ Bl,
    const float* __restrict__ bias, float* __restrict__ C, int ldc)
{
    extern __shared__ __nv_bfloat16 sm[];
    const int t = threadIdx.x;
    const int lane = t & 31;
    const int wid = t >> 5;
    const int wm = wid >> 1;
    const int wn = wid & 1;
    const int n0   = blockIdx.x * 64;
    const int row0 = blockIdx.y * 64;

    // Load A tile (64x192 fp32), split to hi/lo in registers, u64 STS
#pragma unroll
    for (int it = 0; it < 24; it++) {
        int idx = it * 128 + t;
        int r = idx / 48;
        int k = (idx % 48) * 4;
        float4 a = *(const float4*)(A + (size_t)(row0 + r) * KDIM + k);
        uint64_t hi64, lo64;
        split4_64(a, hi64, lo64);
        int s = r * LDSG + k;
        *(uint64_t*)(sm + SM_AH + s) = hi64;
        *(uint64_t*)(sm + SM_AL + s) = lo64;
    }
    // Load B tile (64 n-rows x 192, hi+lo, already bf16)
#pragma unroll
    for (int it = 0; it < 24; it++) {
        int idx = it * 128 + t;
        int r = idx / 48;
        int k = (idx % 48) * 4;
        size_t g = (size_t)(n0 + r) * KDIM + k;
        int s = r * LDSG + k;
        *(uint64_t*)(sm + SM_BH + s) = *(const uint64_t*)(Bh + g);
        *(uint64_t*)(sm + SM_BL + s) = *(const uint64_t*)(Bl + g);
    }
    __syncthreads();

    float acc[2][4][4];
#pragma unroll
    for (int i = 0; i < 2; i++)
#pragma unroll
        for (int j = 0; j < 4; j++)
#pragma unroll
            for (int e = 0; e < 4; e++) acc[i][j][e] = 0.0f;

    const uint32_t sbase = smem_u32(sm);
    const uint32_t aoff = (uint32_t)((wm * 32 + (lane & 15)) * LDSG + ((lane >> 4) << 3));
    const uint32_t boff = (uint32_t)((wn * 32 + (lane & 7) + ((lane >> 4) << 3)) * LDSG
                                     + (((lane >> 3) & 1) << 3));

#pragma unroll
    for (int pass = 0; pass < 3; pass++) {
        const uint32_t aBase = sbase + 2u * (pass == 1 ? SM_AL : SM_AH);
        const uint32_t bBase = sbase + 2u * (pass == 2 ? SM_BL : SM_BH);
#pragma unroll
        for (int ks = 0; ks < 12; ks++) {
            const uint32_t k0 = ks * 16;
            uint32_t a0[4], a1[4], b0[4], b1[4];
            ldsm4(aBase + (aoff + k0) * 2, a0);
            ldsm4(aBase + (aoff + 16 * LDSG + k0) * 2, a1);
            ldsm4(bBase + (boff + k0) * 2, b0);
            ldsm4(bBase + (boff + 16 * LDSG + k0) * 2, b1);

            mma16816(acc[0][0], a0, b0[0], b0[1]);
            mma16816(acc[0][1], a0, b0[2], b0[3]);
            mma16816(acc[0][2], a0, b1[0], b1[1]);
            mma16816(acc[0][3], a0, b1[2], b1[3]);
            mma16816(acc[1][0], a1, b0[0], b0[1]);
            mma16816(acc[1][1], a1, b0[2], b0[3]);
            mma16816(acc[1][2], a1, b1[0], b1[1]);
            mma16816(acc[1][3], a1, b1[2], b1[3]);
        }
    }

    const int r_base = row0 + wm * 32 + (lane >> 2);
    const int c_base = n0 + wn * 32 + (lane & 3) * 2;
#pragma unroll
    for (int nt = 0; nt < 4; nt++) {
        const int col = c_base + nt * 8;
        const float bv0 = bias[col];
        const float bv1 = bias[col + 1];
#pragma unroll
        for (int mt = 0; mt < 2; mt++) {
            const int r = r_base + mt * 16;
            float2 v0 = make_float2(acc[mt][nt][0] + bv0, acc[mt][nt][1] + bv1);
            float2 v1 = make_float2(acc[mt][nt][2] + bv0, acc[mt][nt][3] + bv1);
            *(float2*)(C + (size_t)r * ldc + col)       = v0;
            *(float2*)(C + (size_t)(r + 8) * ldc + col) = v1;
        }
    }
}

// ---------------------------------------------------------------------------
// HMMA attention: one block per (batch, head), 128 threads = 4 warps.
// q/k/v all row-major in SMEM with u64 vectorized STS; PV B-fragments via
// ldmatrix.trans (no transposed scalar stores).
// ---------------------------------------------------------------------------
__global__ __launch_bounds__(128) void attn_kernel(
    const float* __restrict__ qkv, const float* __restrict__ bmat,
    float* __restrict__ out)
{
    const int h = blockIdx.x % NHEAD;
    const int b = blockIdx.x / NHEAD;
    const int t = threadIdx.x;
    const int lane = t & 31;
    const int w = t >> 5;

    __shared__ __nv_bfloat16 qh[64][40], ql[64][40];
    __shared__ __nv_bfloat16 kh[64][40], kl[64][40];
    __shared__ __nv_bfloat16 vh[64][40], vl[64][40];   // row-major [token][d]

    // ---- load + split (all u64 vectorized STS) ----
    {
        const int n = t >> 1;
        const int half = t & 1;
        const float scale = 0.1767766952966369f;  // 1/sqrt(32)
        const float* base = qkv + (size_t)(b * 64 + n) * QKVW + h * HDIM + half * 16;
#pragma unroll
        for (int i = 0; i < 4; i++) {
            float4 qv = *(const float4*)(base + i * 4);
            float4 kv = *(const float4*)(base + 192 + i * 4);
            float4 vv = *(const float4*)(base + 384 + i * 4);
            qv.x *= scale; qv.y *= scale; qv.z *= scale; qv.w *= scale;
            const int c0 = half * 16 + i * 4;
            uint64_t h64, l64;
            split4_64(qv, h64, l64);
            *(uint64_t*)&qh[n][c0] = h64;
            *(uint64_t*)&ql[n][c0] = l64;
            split4_64(kv, h64, l64);
            *(uint64_t*)&kh[n][c0] = h64;
            *(uint64_t*)&kl[n][c0] = l64;
            split4_64(vv, h64, l64);
            *(uint64_t*)&vh[n][c0] = h64;
            *(uint64_t*)&vl[n][c0] = l64;
        }
    }
    __syncthreads();

    // ---- QK^T ----
    float s[8][4];
#pragma unroll
    for (int j = 0; j < 8; j++)
#pragma unroll
        for (int e = 0; e < 4; e++) s[j][e] = 0.0f;

    const uint32_t qhB = smem_u32(&qh[0][0]);
    const uint32_t qlB = smem_u32(&ql[0][0]);
    const uint32_t khB = smem_u32(&kh[0][0]);
    const uint32_t klB = smem_u32(&kl[0][0]);
    const uint32_t aoff = (uint32_t)((16 * w + (lane & 15)) * 40 + ((lane >> 4) << 3));
    const uint32_t boff = (uint32_t)(((lane & 7) + ((lane >> 4) << 3)) * 40
                                     + (((lane >> 3) & 1) << 3));

#pragma unroll
    for (int pass = 0; pass < 3; pass++) {
        const uint32_t aB = (pass == 1) ? qlB : qhB;
        const uint32_t bB = (pass == 2) ? klB : khB;
#pragma unroll
        for (int ks = 0; ks < 2; ks++) {
            uint32_t A[4];
            ldsm4(aB + (aoff + ks * 16) * 2, A);
#pragma unroll
            for (int nt = 0; nt < 4; nt++) {
                uint32_t B[4];
                ldsm4(bB + (boff + nt * 16 * 40 + ks * 16) * 2, B);
                mma16816(s[2 * nt],     A, B[0], B[1]);
                mma16816(s[2 * nt + 1], A, B[2], B[3]);
            }
        }
    }

    // ---- bias + softmax (rows r0 = 16w + lane/4, r1 = r0+8) ----
    const int r0 = 16 * w + (lane >> 2);
    const int cb = 2 * (lane & 3);
    const float* bm = bmat + h * 4096;
#pragma unroll
    for (int j = 0; j < 8; j++) {
        float2 b0 = *(const float2*)(bm + r0 * 64 + 8 * j + cb);
        float2 b1 = *(const float2*)(bm + (r0 + 8) * 64 + 8 * j + cb);
        s[j][0] += b0.x; s[j][1] += b0.y;
        s[j][2] += b1.x; s[j][3] += b1.y;
    }

    float mx0 = -1e30f, mx1 = -1e30f;
#pragma unroll
    for (int j = 0; j < 8; j++) {
        mx0 = fmaxf(mx0, fmaxf(s[j][0], s[j][1]));
        mx1 = fmaxf(mx1, fmaxf(s[j][2], s[j][3]));
    }
    mx0 = fmaxf(mx0, __shfl_xor_sync(0xffffffffu, mx0, 1));
    mx0 = fmaxf(mx0, __shfl_xor_sync(0xffffffffu, mx0, 2));
    mx1 = fmaxf(mx1, __shfl_xor_sync(0xffffffffu, mx1, 1));
    mx1 = fmaxf(mx1, __shfl_xor_sync(0xffffffffu, mx1, 2));

    float sum0 = 0.0f, sum1 = 0.0f;
#pragma unroll
    for (int j = 0; j < 8; j++) {
        s[j][0] = __expf(s[j][0] - mx0); sum0 += s[j][0];
        s[j][1] = __expf(s[j][1] - mx0); sum0 += s[j][1];
        s[j][2] = __expf(s[j][2] - mx1); sum1 += s[j][2];
        s[j][3] = __expf(s[j][3] - mx1); sum1 += s[j][3];
    }
    sum0 += __shfl_xor_sync(0xffffffffu, sum0, 1);
    sum0 += __shfl_xor_sync(0xffffffffu, sum0, 2);
    sum1 += __shfl_xor_sync(0xffffffffu, sum1, 1);
    sum1 += __shfl_xor_sync(0xffffffffu, sum1, 2);
    const float inv0 = 1.0f / sum0;
    const float inv1 = 1.0f / sum1;

    // ---- P -> bf16 hi/lo A-fragments in registers ----
    uint32_t ph[4][4], pl[4][4];
#pragma unroll
    for (int ks = 0; ks < 4; ks++) {
        const int j0 = 2 * ks, j1 = 2 * ks + 1;
        float p[8] = { s[j0][0] * inv0, s[j0][1] * inv0,
                       s[j0][2] * inv1, s[j0][3] * inv1,
                       s[j1][0] * inv0, s[j1][1] * inv0,
                       s[j1][2] * inv1, s[j1][3] * inv1 };
        float hi[8], lo[8];
#pragma unroll
        for (int e = 0; e < 8; e++) {
            __nv_bfloat16 hh = __float2bfloat16(p[e]);
            hi[e] = __bfloat162float(hh);
            lo[e] = p[e] - hi[e];
        }
        ph[ks][0] = packbf2(hi[0], hi[1]); pl[ks][0] = packbf2(lo[0], lo[1]);
        ph[ks][1] = packbf2(hi[2], hi[3]); pl[ks][1] = packbf2(lo[2], lo[3]);
        ph[ks][2] = packbf2(hi[4], hi[5]); pl[ks][2] = packbf2(lo[4], lo[5]);
        ph[ks][3] = packbf2(hi[6], hi[7]); pl[ks][3] = packbf2(lo[6], lo[7]);
    }

    // ---- PV: B-fragments from row-major V via ldmatrix.trans ----
    float o[4][4];
#pragma unroll
    for (int j = 0; j < 4; j++)
#pragma unroll
        for (int e = 0; e < 4; e++) o[j][e] = 0.0f;

    const uint32_t vhB = smem_u32(&vh[0][0]);
    const uint32_t vlB = smem_u32(&vl[0][0]);
    // lanes 0-7: tok r0-7 col0 | 8-15: tok r8-15 col0 | 16-23: tok r0-7 col+8 | 24-31: tok r8-15 col+8
    const uint32_t vtoff = (uint32_t)(((lane & 7) + (((lane >> 3) & 1) << 3)) * 40
                                      + ((lane >> 4) << 3));

#pragma unroll
    for (int pass = 0; pass < 3; pass++) {
        const uint32_t (*A)[4] = (pass == 1) ? pl : ph;
        const uint32_t vB = (pass == 2) ? vlB : vhB;
#pragma unroll
        for (int ks = 0; ks < 4; ks++) {
            uint32_t B0[4], B1[4];
            ldsm4t(vB + (vtoff + ks * 16 * 40) * 2, B0);        // d 0-15
            ldsm4t(vB + (vtoff + ks * 16 * 40 + 16) * 2, B1);   // d 16-31
            mma16816(o[0], A[ks], B0[0], B0[1]);
            mma16816(o[1], A[ks], B0[2], B0[3]);
            mma16816(o[2], A[ks], B1[0], B1[1]);
            mma16816(o[3], A[ks], B1[2], B1[3]);
        }
    }

    // ---- store ----
    float* op = out + (size_t)(b * 64) * CDIM + h * HDIM;
#pragma unroll
    for (int j = 0; j < 4; j++) {
        const int d = 8 * j + cb;
        *(float2*)(op + (size_t)r0 * CDIM + d)       = make_float2(o[j][0], o[j][1]);
        *(float2*)(op + (size_t)(r0 + 8) * CDIM + d) = make_float2(o[j][2], o[j][3]);
    }
}

// ---------------------------------------------------------------------------
// Positional conv branch: 192 threads = 1 channel each.
// v_r loaded straight to registers; depthwise 5x5 in registers; pt chunked
// (2 x 32 pixels) to cut smem to 49 KB -> 2-3 CTAs/SM.
// ---------------------------------------------------------------------------
#define CONV_SMEM ((32 * 192 + 32 * 193) * 4)   // 49280 bytes

__global__ __launch_bounds__(192, 2) void conv_kernel(
    const float* __restrict__ qkv, const float* __restrict__ dw_w,
    const float* __restrict__ dw_b, const float* __restrict__ pw_w,
    const float* __restrict__ pw_b, float* __restrict__ att)
{
    extern __shared__ float smf[];
    float* ptc  = smf;                  // [32][192] depthwise chunk
    float* pw_s = smf + 32 * 192;       // [32][193] pw_s[d][c]

    const int b = blockIdx.x;
    const int c = threadIdx.x;

    // v_r straight to registers (coalesced across c)
    const float* src = qkv + (size_t)b * 64 * QKVW + 576;
    float in[64];
#pragma unroll
    for (int p = 0; p < 64; p++) in[p] = src[(size_t)p * QKVW + c];

    float w[25];
#pragma unroll
    for (int i = 0; i < 25; i++) w[i] = dw_w[c * 25 + i];
    const float db = dw_b[c];

    // Stage pw_w transposed: pw_s[d][cc] = pw_w[cc][d]
#pragma unroll
    for (int i = 0; i < 32; i++) {
        int idx = i * 192 + c;
        int cc = idx >> 5, d = idx & 31;
        pw_s[d * 193 + cc] = pw_w[idx];
    }
    __syncthreads();

    float wv[32];
#pragma unroll
    for (int d = 0; d < 32; d++) wv[d] = pw_s[d * 193 + c];
    const float pb = pw_b[c];
    const int g32 = (c >> 5) << 5;
    float* dst = att + (size_t)b * 64 * CDIM;

#pragma unroll
    for (int ch = 0; ch < 2; ch++) {
        const int pbase = ch * 32;
        // Depthwise 5x5 for this 32-pixel chunk
#pragma unroll
        for (int pp = 0; pp < 32; pp++) {
            const int p = pbase + pp;
            const int y = p >> 3, x = p & 7;
            float a = db;
#pragma unroll
            for (int ky = 0; ky < 5; ky++) {
                const int yy = y + ky - 2;
                if (yy < 0 || yy > 7) continue;
#pragma unroll
                for (int kx = 0; kx < 5; kx++) {
                    const int xx = x + kx - 2;
                    if (xx < 0 || xx > 7) continue;
                    a += in[yy * 8 + xx] * w[ky * 5 + kx];
                }
            }
            ptc[pp * 192 + c] = a;
        }
        __syncthreads();

        // Grouped 1x1 for this chunk, accumulate into attention output
#pragma unroll
        for (int pp = 0; pp < 32; pp++) {
            const float4* pr = (const float4*)(ptc + pp * 192 + g32);
            float a = pb;
#pragma unroll
            for (int d4 = 0; d4 < 8; d4++) {
                float4 v = pr[d4];
                a += v.x * wv[d4 * 4 + 0] + v.y * wv[d4 * 4 + 1]
                   + v.z * wv[d4 * 4 + 2] + v.w * wv[d4 * 4 + 3];
            }
            dst[(pbase + pp) * 192 + c] += a;
        }
        if (ch == 0) __syncthreads();
    }
}

// ---------------------------------------------------------------------------
extern "C" void kernel_launch(void* const* d_in, const int* in_sizes, int n_in,
                              void* d_out, int out_size)
{
    const float* x      = (const float*)d_in[0];
    const float* wq     = (const float*)d_in[1];
    const float* bq     = (const float*)d_in[2];
    const float* wkv    = (const float*)d_in[3];
    const float* bkv    = (const float*)d_in[4];
    const float* rpb    = (const float*)d_in[5];
    const int*   relidx = (const int*)  d_in[6];
    const float* dw_w   = (const float*)d_in[7];
    const float* dw_b   = (const float*)d_in[8];
    const float* pw_w   = (const float*)d_in[9];
    const float* pw_b   = (const float*)d_in[10];
    const float* proj_w = (const float*)d_in[11];
    const float* proj_b = (const float*)d_in[12];
    float* out = (float*)d_out;

    float *qkv, *att, *biasc, *bmat;
    __nv_bfloat16 *wh, *wl, *pwh, *pwl;
    cudaGetSymbolAddress((void**)&qkv,  g_qkv);
    cudaGetSymbolAddress((void**)&att,  g_att);
    cudaGetSymbolAddress((void**)&wh,   g_wh);
    cudaGetSymbolAddress((void**)&wl,   g_wl);
    cudaGetSymbolAddress((void**)&pwh,  g_pwh);
    cudaGetSymbolAddress((void**)&pwl,  g_pwl);
    cudaGetSymbolAddress((void**)&biasc, g_bias);
    cudaGetSymbolAddress((void**)&bmat, g_bmat);

    cudaFuncSetAttribute(gemm_tc_kernel,
                         cudaFuncAttributeMaxDynamicSharedMemorySize, GEMM_SMEM);
    cudaFuncSetAttribute(conv_kernel,
                         cudaFuncAttributeMaxDynamicSharedMemorySize, CONV_SMEM);

    // 0) weight prep (incl. bias matrices)
    prep_w_kernel<<<(768 * 192 + 192 * 192 + 255) / 256, 256>>>(
        wq, wkv, bq, bkv, proj_w, rpb, relidx);

    // 1) fused q|k|v|v_r GEMM (fp32 A, split in-kernel) -> g_qkv
    gemm_tc_kernel<<<dim3(QKVW / 64, MROWS / 64), 128, GEMM_SMEM>>>(
        x, wh, wl, biasc, qkv, QKVW);

    // 2) attention -> g_att (HMMA)
    attn_kernel<<<BATCH * NHEAD, 128>>>(qkv, bmat, att);

    // 3) conv branch accumulates into g_att
    conv_kernel<<<BATCH, 192, CONV_SMEM>>>(qkv, dw_w, dw_b, pw_w, pw_b, att);

    // 4) proj GEMM (fp32 A, split in-kernel) -> d_out
    gemm_tc_kernel<<<dim3(CDIM / 64, MROWS / 64), 128, GEMM_SMEM>>>(
        att, pwh, pwl, proj_b, out, CDIM);
}

// round 13
// speedup vs baseline: 1.6917x; 1.5648x over previous
#include <cuda_runtime.h>
#include <cuda_fp16.h>
#include <cstdint>
#include <cstddef>

// Problem constants
#define BATCH 4096
#define NTOK 64
#define CDIM 192
#define NHEAD 6
#define HDIM 32
#define MROWS (BATCH * NTOK)   // 262144
#define QKVW 768               // q(192) + k(192) + v(192) + v_r(192)
#define KDIM 192

// ---------------------------------------------------------------------------
// Device scratch (no allocations allowed)
// ---------------------------------------------------------------------------
__device__ float g_qkv[(size_t)MROWS * QKVW];          // 805 MB
__device__ float g_att[(size_t)MROWS * CDIM];          // 201 MB
__device__ __half g_wh[768 * 192];                     // qkv weights (N-major) fp16
__device__ __half g_pwh[192 * 192];                    // proj weights (N-major) fp16
__device__ float g_bias[768];                          // concat(bq, bkv)
__device__ float g_bmat[NHEAD * NTOK * NTOK];          // precomputed rel-pos bias

// ---------------------------------------------------------------------------
// MMA helpers (portable on compute_103: ldmatrix + mma.sync are sm_80 features)
// ---------------------------------------------------------------------------
__device__ __forceinline__ uint32_t smem_u32(const void* p) {
    uint32_t a;
    asm("{ .reg .u64 t; cvta.to.shared.u64 t, %1; cvt.u32.u64 %0, t; }"
        : "=r"(a) : "l"(p));
    return a;
}

__device__ __forceinline__ void ldsm4(uint32_t addr, uint32_t r[4]) {
    asm volatile("ldmatrix.sync.aligned.m8n8.x4.shared.b16 {%0,%1,%2,%3}, [%4];"
        : "=r"(r[0]), "=r"(r[1]), "=r"(r[2]), "=r"(r[3]) : "r"(addr));
}

__device__ __forceinline__ void ldsm4t(uint32_t addr, uint32_t r[4]) {
    asm volatile("ldmatrix.sync.aligned.m8n8.x4.trans.shared.b16 {%0,%1,%2,%3}, [%4];"
        : "=r"(r[0]), "=r"(r[1]), "=r"(r[2]), "=r"(r[3]) : "r"(addr));
}

__device__ __forceinline__ void mma16816(float c[4], const uint32_t a[4],
                                         uint32_t b0, uint32_t b1) {
    asm volatile(
        "mma.sync.aligned.m16n8k16.row.col.f32.f16.f16.f32 "
        "{%0,%1,%2,%3}, {%4,%5,%6,%7}, {%8,%9}, {%0,%1,%2,%3};"
        : "+f"(c[0]), "+f"(c[1]), "+f"(c[2]), "+f"(c[3])
        : "r"(a[0]), "r"(a[1]), "r"(a[2]), "r"(a[3]), "r"(b0), "r"(b1));
}

__device__ __forceinline__ uint32_t packh2(float a, float b) {
    __half2 t = __floats2half2_rn(a, b);
    return *(uint32_t*)&t;
}

// float4 -> 4 fp16 packed into u64
__device__ __forceinline__ uint64_t pack4h(const float4 v) {
    __half2 h01 = __floats2half2_rn(v.x, v.y);
    __half2 h23 = __floats2half2_rn(v.z, v.w);
    return ((uint64_t)*(uint32_t*)&h23 << 32) | *(uint32_t*)&h01;
}

// Split float4 -> fp16 hi (u64) and fp16 lo (u64)
__device__ __forceinline__ void split4h_64(const float4 v, uint64_t& hi64, uint64_t& lo64) {
    __half2 h01 = __floats2half2_rn(v.x, v.y);
    __half2 h23 = __floats2half2_rn(v.z, v.w);
    float2 r01 = __half22float2(h01);
    float2 r23 = __half22float2(h23);
    __half2 l01 = __floats2half2_rn(v.x - r01.x, v.y - r01.y);
    __half2 l23 = __floats2half2_rn(v.z - r23.x, v.w - r23.y);
    hi64 = ((uint64_t)*(uint32_t*)&h23 << 32) | *(uint32_t*)&h01;
    lo64 = ((uint64_t)*(uint32_t*)&l23 << 32) | *(uint32_t*)&l01;
}

// Weights: transpose to N-major [n][k], fp16; concat biases; bias matrices.
__global__ __launch_bounds__(256) void prep_w_kernel(
    const float* __restrict__ wq, const float* __restrict__ wkv,
    const float* __restrict__ bq, const float* __restrict__ bkv,
    const float* __restrict__ projw,
    const float* __restrict__ rpb, const int* __restrict__ relidx)
{
    int idx = blockIdx.x * 256 + threadIdx.x;
    if (idx < 768 * 192) {
        int n = idx / 192, k = idx % 192;
        float v = (n < 192) ? wq[k * 192 + n] : wkv[k * 576 + (n - 192)];
        g_wh[idx] = __float2half_rn(v);
    } else if (idx < 768 * 192 + 192 * 192) {
        int j = idx - 768 * 192;
        int n = j / 192, k = j % 192;
        g_pwh[j] = __float2half_rn(projw[k * 192 + n]);
    }
    if (idx < 768) g_bias[idx] = (idx < 192) ? bq[idx] : bkv[idx - 192];
    if (idx < NTOK * NTOK) {
        int ri = relidx[idx];
#pragma unroll
        for (int h = 0; h < NHEAD; h++)
            g_bmat[h * (NTOK * NTOK) + idx] = rpb[ri * NHEAD + h];
    }
}

// ---------------------------------------------------------------------------
// HMMA GEMM: C[64x64 tile] = (Ah+Al)[64xK] @ Bh^T[Kx64] + bias
// A fp32 split to fp16 hi/lo in load phase; B single fp16. 2-pass fused:
// per k-step load B once, issue hi-A and lo-A MMAs. K=192 SMEM-resident.
// ---------------------------------------------------------------------------
#define LDSG 200
#define SM_AH 0
#define SM_AL (64 * LDSG)
#define SM_BH (128 * LDSG)
#define GEMM_SMEM (192 * LDSG * 2)     // 76800 bytes -> 2 CTAs/SM

__global__ __launch_bounds__(128) void gemm_tc_kernel(
    const float* __restrict__ A, const __half* __restrict__ Bh,
    const float* __restrict__ bias, float* __restrict__ C, int ldc)
{
    extern __shared__ __half sm[];
    const int t = threadIdx.x;
    const int lane = t & 31;
    const int wid = t >> 5;
    const int wm = wid >> 1;
    const int wn = wid & 1;
    const int n0   = blockIdx.x * 64;
    const int row0 = blockIdx.y * 64;

    // Load A tile (64x192 fp32), split to fp16 hi/lo, u64 STS
#pragma unroll
    for (int it = 0; it < 24; it++) {
        int idx = it * 128 + t;
        int r = idx / 48;
        int k = (idx % 48) * 4;
        float4 a = *(const float4*)(A + (size_t)(row0 + r) * KDIM + k);
        uint64_t hi64, lo64;
        split4h_64(a, hi64, lo64);
        int s = r * LDSG + k;
        *(uint64_t*)(sm + SM_AH + s) = hi64;
        *(uint64_t*)(sm + SM_AL + s) = lo64;
    }
    // Load B tile (64 n-rows x 192 fp16)
#pragma unroll
    for (int it = 0; it < 12; it++) {
        int idx = it * 128 + t;
        int r = idx / 24;
        int k = (idx % 24) * 8;
        size_t g = (size_t)(n0 + r) * KDIM + k;
        int s = r * LDSG + k;
        *(uint4*)(sm + SM_BH + s) = *(const uint4*)(Bh + g);
    }
    __syncthreads();

    float acc[2][4][4];
#pragma unroll
    for (int i = 0; i < 2; i++)
#pragma unroll
        for (int j = 0; j < 4; j++)
#pragma unroll
            for (int e = 0; e < 4; e++) acc[i][j][e] = 0.0f;

    const uint32_t sbase = smem_u32(sm);
    const uint32_t aoff = (uint32_t)((wm * 32 + (lane & 15)) * LDSG + ((lane >> 4) << 3));
    const uint32_t boff = (uint32_t)((wn * 32 + (lane & 7) + ((lane >> 4) << 3)) * LDSG
                                     + (((lane >> 3) & 1) << 3));
    const uint32_t aH = sbase + 2u * SM_AH;
    const uint32_t aL = sbase + 2u * SM_AL;
    const uint32_t bB = sbase + 2u * SM_BH;

#pragma unroll
    for (int ks = 0; ks < 12; ks++) {
        const uint32_t k0 = ks * 16;
        uint32_t ah0[4], ah1[4], al0[4], al1[4], b0[4], b1[4];
        ldsm4(aH + (aoff + k0) * 2, ah0);
        ldsm4(aH + (aoff + 16 * LDSG + k0) * 2, ah1);
        ldsm4(aL + (aoff + k0) * 2, al0);
        ldsm4(aL + (aoff + 16 * LDSG + k0) * 2, al1);
        ldsm4(bB + (boff + k0) * 2, b0);
        ldsm4(bB + (boff + 16 * LDSG + k0) * 2, b1);

        mma16816(acc[0][0], ah0, b0[0], b0[1]);
        mma16816(acc[0][1], ah0, b0[2], b0[3]);
        mma16816(acc[0][2], ah0, b1[0], b1[1]);
        mma16816(acc[0][3], ah0, b1[2], b1[3]);
        mma16816(acc[1][0], ah1, b0[0], b0[1]);
        mma16816(acc[1][1], ah1, b0[2], b0[3]);
        mma16816(acc[1][2], ah1, b1[0], b1[1]);
        mma16816(acc[1][3], ah1, b1[2], b1[3]);

        mma16816(acc[0][0], al0, b0[0], b0[1]);
        mma16816(acc[0][1], al0, b0[2], b0[3]);
        mma16816(acc[0][2], al0, b1[0], b1[1]);
        mma16816(acc[0][3], al0, b1[2], b1[3]);
        mma16816(acc[1][0], al1, b0[0], b0[1]);
        mma16816(acc[1][1], al1, b0[2], b0[3]);
        mma16816(acc[1][2], al1, b1[0], b1[1]);
        mma16816(acc[1][3], al1, b1[2], b1[3]);
    }

    const int r_base = row0 + wm * 32 + (lane >> 2);
    const int c_base = n0 + wn * 32 + (lane & 3) * 2;
#pragma unroll
    for (int nt = 0; nt < 4; nt++) {
        const int col = c_base + nt * 8;
        const float bv0 = bias[col];
        const float bv1 = bias[col + 1];
#pragma unroll
        for (int mt = 0; mt < 2; mt++) {
            const int r = r_base + mt * 16;
            float2 v0 = make_float2(acc[mt][nt][0] + bv0, acc[mt][nt][1] + bv1);
            float2 v1 = make_float2(acc[mt][nt][2] + bv0, acc[mt][nt][3] + bv1);
            *(float2*)(C + (size_t)r * ldc + col)       = v0;
            *(float2*)(C + (size_t)(r + 8) * ldc + col) = v1;
        }
    }
}

// ---------------------------------------------------------------------------
// HMMA attention: one block per (batch, head), 128 threads = 4 warps.
// q split fp16 hi/lo (2-pass QK); k, v single fp16. PV: P split hi/lo in
// registers (2-pass), V B-fragments via ldmatrix.trans.
// ---------------------------------------------------------------------------
__global__ __launch_bounds__(128) void attn_kernel(
    const float* __restrict__ qkv, const float* __restrict__ bmat,
    float* __restrict__ out)
{
    const int h = blockIdx.x % NHEAD;
    const int b = blockIdx.x / NHEAD;
    const int t = threadIdx.x;
    const int lane = t & 31;
    const int w = t >> 5;

    __shared__ __half qh[64][40], ql[64][40];
    __shared__ __half kh[64][40];
    __shared__ __half vh[64][40];   // row-major [token][d]

    // ---- load + convert (u64 vectorized STS) ----
    {
        const int n = t >> 1;
        const int half_ = t & 1;
        const float scale = 0.1767766952966369f;  // 1/sqrt(32)
        const float* base = qkv + (size_t)(b * 64 + n) * QKVW + h * HDIM + half_ * 16;
#pragma unroll
        for (int i = 0; i < 4; i++) {
            float4 qv = *(const float4*)(base + i * 4);
            float4 kv = *(const float4*)(base + 192 + i * 4);
            float4 vv = *(const float4*)(base + 384 + i * 4);
            qv.x *= scale; qv.y *= scale; qv.z *= scale; qv.w *= scale;
            const int c0 = half_ * 16 + i * 4;
            uint64_t h64, l64;
            split4h_64(qv, h64, l64);
            *(uint64_t*)&qh[n][c0] = h64;
            *(uint64_t*)&ql[n][c0] = l64;
            *(uint64_t*)&kh[n][c0] = pack4h(kv);
            *(uint64_t*)&vh[n][c0] = pack4h(vv);
        }
    }
    __syncthreads();

    // ---- QK^T (2-pass fused: B loaded once per nt) ----
    float s[8][4];
#pragma unroll
    for (int j = 0; j < 8; j++)
#pragma unroll
        for (int e = 0; e < 4; e++) s[j][e] = 0.0f;

    const uint32_t qhB = smem_u32(&qh[0][0]);
    const uint32_t qlB = smem_u32(&ql[0][0]);
    const uint32_t khB = smem_u32(&kh[0][0]);
    const uint32_t aoff = (uint32_t)((16 * w + (lane & 15)) * 40 + ((lane >> 4) << 3));
    const uint32_t boff = (uint32_t)(((lane & 7) + ((lane >> 4) << 3)) * 40
                                     + (((lane >> 3) & 1) << 3));

#pragma unroll
    for (int ks = 0; ks < 2; ks++) {
        uint32_t Ah[4], Al[4];
        ldsm4(qhB + (aoff + ks * 16) * 2, Ah);
        ldsm4(qlB + (aoff + ks * 16) * 2, Al);
#pragma unroll
        for (int nt = 0; nt < 4; nt++) {
            uint32_t B[4];
            ldsm4(khB + (boff + nt * 16 * 40 + ks * 16) * 2, B);
            mma16816(s[2 * nt],     Ah, B[0], B[1]);
            mma16816(s[2 * nt + 1], Ah, B[2], B[3]);
            mma16816(s[2 * nt],     Al, B[0], B[1]);
            mma16816(s[2 * nt + 1], Al, B[2], B[3]);
        }
    }

    // ---- bias + softmax (rows r0 = 16w + lane/4, r1 = r0+8) ----
    const int r0 = 16 * w + (lane >> 2);
    const int cb = 2 * (lane & 3);
    const float* bm = bmat + h * 4096;
#pragma unroll
    for (int j = 0; j < 8; j++) {
        float2 b0 = *(const float2*)(bm + r0 * 64 + 8 * j + cb);
        float2 b1 = *(const float2*)(bm + (r0 + 8) * 64 + 8 * j + cb);
        s[j][0] += b0.x; s[j][1] += b0.y;
        s[j][2] += b1.x; s[j][3] += b1.y;
    }

    float mx0 = -1e30f, mx1 = -1e30f;
#pragma unroll
    for (int j = 0; j < 8; j++) {
        mx0 = fmaxf(mx0, fmaxf(s[j][0], s[j][1]));
        mx1 = fmaxf(mx1, fmaxf(s[j][2], s[j][3]));
    }
    mx0 = fmaxf(mx0, __shfl_xor_sync(0xffffffffu, mx0, 1));
    mx0 = fmaxf(mx0, __shfl_xor_sync(0xffffffffu, mx0, 2));
    mx1 = fmaxf(mx1, __shfl_xor_sync(0xffffffffu, mx1, 1));
    mx1 = fmaxf(mx1, __shfl_xor_sync(0xffffffffu, mx1, 2));

    float sum0 = 0.0f, sum1 = 0.0f;
#pragma unroll
    for (int j = 0; j < 8; j++) {
        s[j][0] = __expf(s[j][0] - mx0); sum0 += s[j][0];
        s[j][1] = __expf(s[j][1] - mx0); sum0 += s[j][1];
        s[j][2] = __expf(s[j][2] - mx1); sum1 += s[j][2];
        s[j][3] = __expf(s[j][3] - mx1); sum1 += s[j][3];
    }
    sum0 += __shfl_xor_sync(0xffffffffu, sum0, 1);
    sum0 += __shfl_xor_sync(0xffffffffu, sum0, 2);
    sum1 += __shfl_xor_sync(0xffffffffu, sum1, 1);
    sum1 += __shfl_xor_sync(0xffffffffu, sum1, 2);
    const float inv0 = 1.0f / sum0;
    const float inv1 = 1.0f / sum1;

    // ---- P -> fp16 hi/lo A-fragments in registers ----
    uint32_t ph[4][4], pl[4][4];
#pragma unroll
    for (int ks = 0; ks < 4; ks++) {
        const int j0 = 2 * ks, j1 = 2 * ks + 1;
        float p[8] = { s[j0][0] * inv0, s[j0][1] * inv0,
                       s[j0][2] * inv1, s[j0][3] * inv1,
                       s[j1][0] * inv0, s[j1][1] * inv0,
                       s[j1][2] * inv1, s[j1][3] * inv1 };
        float hi[8], lo[8];
#pragma unroll
        for (int e = 0; e < 8; e++) {
            __half hh = __float2half_rn(p[e]);
            hi[e] = __half2float(hh);
            lo[e] = p[e] - hi[e];
        }
        ph[ks][0] = packh2(hi[0], hi[1]); pl[ks][0] = packh2(lo[0], lo[1]);
        ph[ks][1] = packh2(hi[2], hi[3]); pl[ks][1] = packh2(lo[2], lo[3]);
        ph[ks][2] = packh2(hi[4], hi[5]); pl[ks][2] = packh2(lo[4], lo[5]);
        ph[ks][3] = packh2(hi[6], hi[7]); pl[ks][3] = packh2(lo[6], lo[7]);
    }

    // ---- PV (2-pass fused): B-fragments from row-major V via ldmatrix.trans ----
    float o[4][4];
#pragma unroll
    for (int j = 0; j < 4; j++)
#pragma unroll
        for (int e = 0; e < 4; e++) o[j][e] = 0.0f;

    const uint32_t vhB = smem_u32(&vh[0][0]);
    const uint32_t vtoff = (uint32_t)(((lane & 7) + (((lane >> 3) & 1) << 3)) * 40
                                      + ((lane >> 4) << 3));

#pragma unroll
    for (int ks = 0; ks < 4; ks++) {
        uint32_t B0[4], B1[4];
        ldsm4t(vhB + (vtoff + ks * 16 * 40) * 2, B0);        // d 0-15
        ldsm4t(vhB + (vtoff + ks * 16 * 40 + 16) * 2, B1);   // d 16-31
        mma16816(o[0], ph[ks], B0[0], B0[1]);
        mma16816(o[1], ph[ks], B0[2], B0[3]);
        mma16816(o[2], ph[ks], B1[0], B1[1]);
        mma16816(o[3], ph[ks], B1[2], B1[3]);
        mma16816(o[0], pl[ks], B0[0], B0[1]);
        mma16816(o[1], pl[ks], B0[2], B0[3]);
        mma16816(o[2], pl[ks], B1[0], B1[1]);
        mma16816(o[3], pl[ks], B1[2], B1[3]);
    }

    // ---- store ----
    float* op = out + (size_t)(b * 64) * CDIM + h * HDIM;
#pragma unroll
    for (int j = 0; j < 4; j++) {
        const int d = 8 * j + cb;
        *(float2*)(op + (size_t)r0 * CDIM + d)       = make_float2(o[j][0], o[j][1]);
        *(float2*)(op + (size_t)(r0 + 8) * CDIM + d) = make_float2(o[j][2], o[j][3]);
    }
}

// ---------------------------------------------------------------------------
// Positional conv branch (validated in R11, unchanged)
// ---------------------------------------------------------------------------
#define CONV_SMEM ((32 * 192 + 32 * 193) * 4)   // 49280 bytes

__global__ __launch_bounds__(192, 2) void conv_kernel(
    const float* __restrict__ qkv, const float* __restrict__ dw_w,
    const float* __restrict__ dw_b, const float* __restrict__ pw_w,
    const float* __restrict__ pw_b, float* __restrict__ att)
{
    extern __shared__ float smf[];
    float* ptc  = smf;                  // [32][192] depthwise chunk
    float* pw_s = smf + 32 * 192;       // [32][193] pw_s[d][c]

    const int b = blockIdx.x;
    const int c = threadIdx.x;

    const float* src = qkv + (size_t)b * 64 * QKVW + 576;
    float in[64];
#pragma unroll
    for (int p = 0; p < 64; p++) in[p] = src[(size_t)p * QKVW + c];

    float w[25];
#pragma unroll
    for (int i = 0; i < 25; i++) w[i] = dw_w[c * 25 + i];
    const float db = dw_b[c];

#pragma unroll
    for (int i = 0; i < 32; i++) {
        int idx = i * 192 + c;
        int cc = idx >> 5, d = idx & 31;
        pw_s[d * 193 + cc] = pw_w[idx];
    }
    __syncthreads();

    float wv[32];
#pragma unroll
    for (int d = 0; d < 32; d++) wv[d] = pw_s[d * 193 + c];
    const float pb = pw_b[c];
    const int g32 = (c >> 5) << 5;
    float* dst = att + (size_t)b * 64 * CDIM;

#pragma unroll
    for (int ch = 0; ch < 2; ch++) {
        const int pbase = ch * 32;
#pragma unroll
        for (int pp = 0; pp < 32; pp++) {
            const int p = pbase + pp;
            const int y = p >> 3, x = p & 7;
            float a = db;
#pragma unroll
            for (int ky = 0; ky < 5; ky++) {
                const int yy = y + ky - 2;
                if (yy < 0 || yy > 7) continue;
#pragma unroll
                for (int kx = 0; kx < 5; kx++) {
                    const int xx = x + kx - 2;
                    if (xx < 0 || xx > 7) continue;
                    a += in[yy * 8 + xx] * w[ky * 5 + kx];
                }
            }
            ptc[pp * 192 + c] = a;
        }
        __syncthreads();

#pragma unroll
        for (int pp = 0; pp < 32; pp++) {
            const float4* pr = (const float4*)(ptc + pp * 192 + g32);
            float a = pb;
#pragma unroll
            for (int d4 = 0; d4 < 8; d4++) {
                float4 v = pr[d4];
                a += v.x * wv[d4 * 4 + 0] + v.y * wv[d4 * 4 + 1]
                   + v.z * wv[d4 * 4 + 2] + v.w * wv[d4 * 4 + 3];
            }
            dst[(pbase + pp) * 192 + c] += a;
        }
        if (ch == 0) __syncthreads();
    }
}

// ---------------------------------------------------------------------------
extern "C" void kernel_launch(void* const* d_in, const int* in_sizes, int n_in,
                              void* d_out, int out_size)
{
    const float* x      = (const float*)d_in[0];
    const float* wq     = (const float*)d_in[1];
    const float* bq     = (const float*)d_in[2];
    const float* wkv    = (const float*)d_in[3];
    const float* bkv    = (const float*)d_in[4];
    const float* rpb    = (const float*)d_in[5];
    const int*   relidx = (const int*)  d_in[6];
    const float* dw_w   = (const float*)d_in[7];
    const float* dw_b   = (const float*)d_in[8];
    const float* pw_w   = (const float*)d_in[9];
    const float* pw_b   = (const float*)d_in[10];
    const float* proj_w = (const float*)d_in[11];
    const float* proj_b = (const float*)d_in[12];
    float* out = (float*)d_out;

    float *qkv, *att, *biasc, *bmat;
    __half *wh, *pwh;
    cudaGetSymbolAddress((void**)&qkv,  g_qkv);
    cudaGetSymbolAddress((void**)&att,  g_att);
    cudaGetSymbolAddress((void**)&wh,   g_wh);
    cudaGetSymbolAddress((void**)&pwh,  g_pwh);
    cudaGetSymbolAddress((void**)&biasc, g_bias);
    cudaGetSymbolAddress((void**)&bmat, g_bmat);

    cudaFuncSetAttribute(gemm_tc_kernel,
                         cudaFuncAttributeMaxDynamicSharedMemorySize, GEMM_SMEM);
    cudaFuncSetAttribute(conv_kernel,
                         cudaFuncAttributeMaxDynamicSharedMemorySize, CONV_SMEM);

    // 0) weight prep (fp16) + bias matrices
    prep_w_kernel<<<(768 * 192 + 192 * 192 + 255) / 256, 256>>>(
        wq, wkv, bq, bkv, proj_w, rpb, relidx);

    // 1) fused q|k|v|v_r GEMM (fp32 A split in-kernel, fp16 2-pass) -> g_qkv
    gemm_tc_kernel<<<dim3(QKVW / 64, MROWS / 64), 128, GEMM_SMEM>>>(
        x, wh, biasc, qkv, QKVW);

    // 2) attention -> g_att (HMMA fp16 2-pass)
    attn_kernel<<<BATCH * NHEAD, 128>>>(qkv, bmat, att);

    // 3) conv branch accumulates into g_att
    conv_kernel<<<BATCH, 192, CONV_SMEM>>>(qkv, dw_w, dw_b, pw_w, pw_b, att);

    // 4) proj GEMM -> d_out
    gemm_tc_kernel<<<dim3(CDIM / 64, MROWS / 64), 128, GEMM_SMEM>>>(
        att, pwh, proj_b, out, CDIM);
}

// round 17
// speedup vs baseline: 1.7823x; 1.0535x over previous
#include <cuda_runtime.h>
#include <cuda_fp16.h>
#include <cstdint>
#include <cstddef>

// Problem constants
#define BATCH 4096
#define NTOK 64
#define CDIM 192
#define NHEAD 6
#define HDIM 32
#define MROWS (BATCH * NTOK)   // 262144
#define KDIM 192

// ---------------------------------------------------------------------------
// Device scratch (no allocations allowed)
// ---------------------------------------------------------------------------
__device__ float  g_q [(size_t)MROWS * 192];           // q   (fp32)
__device__ __half g_kv[(size_t)MROWS * 384];           // k|v (fp16)
__device__ float  g_vr[(size_t)MROWS * 192];           // v_r (fp32, conv input)
__device__ float  g_att[(size_t)MROWS * CDIM];         // attn + conv accumulator
__device__ __half g_wh[768 * 192];                     // qkv weights (N-major) fp16
__device__ __half g_pwh[192 * 192];                    // proj weights (N-major) fp16
__device__ float  g_bias[768];                         // concat(bq, bkv)
__device__ float  g_bmat[NHEAD * NTOK * NTOK];         // precomputed rel-pos bias

// ---------------------------------------------------------------------------
// MMA helpers
// ---------------------------------------------------------------------------
__device__ __forceinline__ uint32_t smem_u32(const void* p) {
    uint32_t a;
    asm("{ .reg .u64 t; cvta.to.shared.u64 t, %1; cvt.u32.u64 %0, t; }"
        : "=r"(a) : "l"(p));
    return a;
}

__device__ __forceinline__ void ldsm4(uint32_t addr, uint32_t r[4]) {
    asm volatile("ldmatrix.sync.aligned.m8n8.x4.shared.b16 {%0,%1,%2,%3}, [%4];"
        : "=r"(r[0]), "=r"(r[1]), "=r"(r[2]), "=r"(r[3]) : "r"(addr));
}

__device__ __forceinline__ void ldsm4t(uint32_t addr, uint32_t r[4]) {
    asm volatile("ldmatrix.sync.aligned.m8n8.x4.trans.shared.b16 {%0,%1,%2,%3}, [%4];"
        : "=r"(r[0]), "=r"(r[1]), "=r"(r[2]), "=r"(r[3]) : "r"(addr));
}

__device__ __forceinline__ void mma16816(float c[4], const uint32_t a[4],
                                         uint32_t b0, uint32_t b1) {
    asm volatile(
        "mma.sync.aligned.m16n8k16.row.col.f32.f16.f16.f32 "
        "{%0,%1,%2,%3}, {%4,%5,%6,%7}, {%8,%9}, {%0,%1,%2,%3};"
        : "+f"(c[0]), "+f"(c[1]), "+f"(c[2]), "+f"(c[3])
        : "r"(a[0]), "r"(a[1]), "r"(a[2]), "r"(a[3]), "r"(b0), "r"(b1));
}

__device__ __forceinline__ uint32_t packh2(float a, float b) {
    __half2 t = __floats2half2_rn(a, b);
    return *(uint32_t*)&t;
}

__device__ __forceinline__ uint64_t pack4h(const float4 v) {
    __half2 h01 = __floats2half2_rn(v.x, v.y);
    __half2 h23 = __floats2half2_rn(v.z, v.w);
    return ((uint64_t)*(uint32_t*)&h23 << 32) | *(uint32_t*)&h01;
}

__device__ __forceinline__ void split4h_64(const float4 v, uint64_t& hi64, uint64_t& lo64) {
    __half2 h01 = __floats2half2_rn(v.x, v.y);
    __half2 h23 = __floats2half2_rn(v.z, v.w);
    float2 r01 = __half22float2(h01);
    float2 r23 = __half22float2(h23);
    __half2 l01 = __floats2half2_rn(v.x - r01.x, v.y - r01.y);
    __half2 l23 = __floats2half2_rn(v.z - r23.x, v.w - r23.y);
    hi64 = ((uint64_t)*(uint32_t*)&h23 << 32) | *(uint32_t*)&h01;
    lo64 = ((uint64_t)*(uint32_t*)&l23 << 32) | *(uint32_t*)&l01;
}

// Weights: transpose to N-major [n][k], fp16; concat biases; bias matrices.
__global__ __launch_bounds__(256) void prep_w_kernel(
    const float* __restrict__ wq, const float* __restrict__ wkv,
    const float* __restrict__ bq, const float* __restrict__ bkv,
    const float* __restrict__ projw,
    const float* __restrict__ rpb, const int* __restrict__ relidx)
{
    int idx = blockIdx.x * 256 + threadIdx.x;
    if (idx < 768 * 192) {
        int n = idx / 192, k = idx % 192;
        float v = (n < 192) ? wq[k * 192 + n] : wkv[k * 576 + (n - 192)];
        g_wh[idx] = __float2half_rn(v);
    } else if (idx < 768 * 192 + 192 * 192) {
        int j = idx - 768 * 192;
        int n = j / 192, k = j % 192;
        g_pwh[j] = __float2half_rn(projw[k * 192 + n]);
    }
    if (idx < 768) g_bias[idx] = (idx < 192) ? bq[idx] : bkv[idx - 192];
    if (idx < NTOK * NTOK) {
        int ri = relidx[idx];
#pragma unroll
        for (int h = 0; h < NHEAD; h++)
            g_bmat[h * (NTOK * NTOK) + idx] = rpb[ri * NHEAD + h];
    }
}

// ---------------------------------------------------------------------------
// HMMA GEMM (templated): C[64x64 tile] = A[64xK] @ Bh^T[Kx64] + bias
// PASSES=2: fp16 hi/lo split of A. PASSES=1: single fp16 A.
// HALF_OUT=1: store C as fp16. K=192 SMEM-resident.
// ---------------------------------------------------------------------------
#define LDSG 200
#define SM_AH 0
#define SM_AL (64 * LDSG)
#define SM_BH (128 * LDSG)
#define GEMM_SMEM (192 * LDSG * 2)     // 76800 bytes

template<int PASSES, int HALF_OUT>
__global__ __launch_bounds__(128) void gemm_tc_kernel(
    const float* __restrict__ A, const __half* __restrict__ Bh,
    const float* __restrict__ bias, void* __restrict__ Cv, int ldc)
{
    extern __shared__ __half sm[];
    const int t = threadIdx.x;
    const int lane = t & 31;
    const int wid = t >> 5;
    const int wm = wid >> 1;
    const int wn = wid & 1;
    const int n0   = blockIdx.x * 64;
    const int row0 = blockIdx.y * 64;

#pragma unroll
    for (int it = 0; it < 24; it++) {
        int idx = it * 128 + t;
        int r = idx / 48;
        int k = (idx % 48) * 4;
        float4 a = *(const float4*)(A + (size_t)(row0 + r) * KDIM + k);
        int s = r * LDSG + k;
        if (PASSES == 2) {
            uint64_t hi64, lo64;
            split4h_64(a, hi64, lo64);
            *(uint64_t*)(sm + SM_AH + s) = hi64;
            *(uint64_t*)(sm + SM_AL + s) = lo64;
        } else {
            *(uint64_t*)(sm + SM_AH + s) = pack4h(a);
        }
    }
#pragma unroll
    for (int it = 0; it < 12; it++) {
        int idx = it * 128 + t;
        int r = idx / 24;
        int k = (idx % 24) * 8;
        size_t g = (size_t)(n0 + r) * KDIM + k;
        int s = r * LDSG + k;
        *(uint4*)(sm + SM_BH + s) = *(const uint4*)(Bh + g);
    }
    __syncthreads();

    float acc[2][4][4];
#pragma unroll
    for (int i = 0; i < 2; i++)
#pragma unroll
        for (int j = 0; j < 4; j++)
#pragma unroll
            for (int e = 0; e < 4; e++) acc[i][j][e] = 0.0f;

    const uint32_t sbase = smem_u32(sm);
    const uint32_t aoff = (uint32_t)((wm * 32 + (lane & 15)) * LDSG + ((lane >> 4) << 3));
    const uint32_t boff = (uint32_t)((wn * 32 + (lane & 7) + ((lane >> 4) << 3)) * LDSG
                                     + (((lane >> 3) & 1) << 3));
    const uint32_t aH = sbase + 2u * SM_AH;
    const uint32_t aL = sbase + 2u * SM_AL;
    const uint32_t bB = sbase + 2u * SM_BH;

#pragma unroll
    for (int ks = 0; ks < 12; ks++) {
        const uint32_t k0 = ks * 16;
        uint32_t ah0[4], ah1[4], b0[4], b1[4];
        ldsm4(aH + (aoff + k0) * 2, ah0);
        ldsm4(aH + (aoff + 16 * LDSG + k0) * 2, ah1);
        ldsm4(bB + (boff + k0) * 2, b0);
        ldsm4(bB + (boff + 16 * LDSG + k0) * 2, b1);

        mma16816(acc[0][0], ah0, b0[0], b0[1]);
        mma16816(acc[0][1], ah0, b0[2], b0[3]);
        mma16816(acc[0][2], ah0, b1[0], b1[1]);
        mma16816(acc[0][3], ah0, b1[2], b1[3]);
        mma16816(acc[1][0], ah1, b0[0], b0[1]);
        mma16816(acc[1][1], ah1, b0[2], b0[3]);
        mma16816(acc[1][2], ah1, b1[0], b1[1]);
        mma16816(acc[1][3], ah1, b1[2], b1[3]);

        if (PASSES == 2) {
            uint32_t al0[4], al1[4];
            ldsm4(aL + (aoff + k0) * 2, al0);
            ldsm4(aL + (aoff + 16 * LDSG + k0) * 2, al1);
            mma16816(acc[0][0], al0, b0[0], b0[1]);
            mma16816(acc[0][1], al0, b0[2], b0[3]);
            mma16816(acc[0][2], al0, b1[0], b1[1]);
            mma16816(acc[0][3], al0, b1[2], b1[3]);
            mma16816(acc[1][0], al1, b0[0], b0[1]);
            mma16816(acc[1][1], al1, b0[2], b0[3]);
            mma16816(acc[1][2], al1, b1[0], b1[1]);
            mma16816(acc[1][3], al1, b1[2], b1[3]);
        }
    }

    const int r_base = row0 + wm * 32 + (lane >> 2);
    const int c_base = n0 + wn * 32 + (lane & 3) * 2;
#pragma unroll
    for (int nt = 0; nt < 4; nt++) {
        const int col = c_base + nt * 8;
        const float bv0 = bias[col];
        const float bv1 = bias[col + 1];
#pragma unroll
        for (int mt = 0; mt < 2; mt++) {
            const int r = r_base + mt * 16;
            if (HALF_OUT) {
                __half* Ch = (__half*)Cv;
                *(uint32_t*)(Ch + (size_t)r * ldc + col) =
                    packh2(acc[mt][nt][0] + bv0, acc[mt][nt][1] + bv1);
                *(uint32_t*)(Ch + (size_t)(r + 8) * ldc + col) =
                    packh2(acc[mt][nt][2] + bv0, acc[mt][nt][3] + bv1);
            } else {
                float* C = (float*)Cv;
                *(float2*)(C + (size_t)r * ldc + col) =
                    make_float2(acc[mt][nt][0] + bv0, acc[mt][nt][1] + bv1);
                *(float2*)(C + (size_t)(r + 8) * ldc + col) =
                    make_float2(acc[mt][nt][2] + bv0, acc[mt][nt][3] + bv1);
            }
        }
    }
}

// ---------------------------------------------------------------------------
// HMMA attention: one block per (batch, head), 128 threads = 4 warps.
// q fp32 -> fp16 hi/lo (2-pass QK); k, v already fp16 (passthrough, FULL
// 16-half copy per thread -- 2x uint4).
// ---------------------------------------------------------------------------
__global__ __launch_bounds__(128) void attn_kernel(
    const float* __restrict__ q, const __half* __restrict__ kv,
    const float* __restrict__ bmat, float* __restrict__ out)
{
    const int h = blockIdx.x % NHEAD;
    const int b = blockIdx.x / NHEAD;
    const int t = threadIdx.x;
    const int lane = t & 31;
    const int w = t >> 5;

    __shared__ __half qh[64][40], ql[64][40];
    __shared__ __half kh[64][40];
    __shared__ __half vh[64][40];   // row-major [token][d]

    // ---- load ----
    {
        const int n = t >> 1;
        const int half_ = t & 1;
        const float scale = 0.1767766952966369f;  // 1/sqrt(32)
        const int c0 = half_ * 16;
        const float* baseq = q + (size_t)(b * 64 + n) * 192 + h * HDIM + c0;
        const __half* basekv = kv + (size_t)(b * 64 + n) * 384 + h * HDIM + c0;
#pragma unroll
        for (int i = 0; i < 4; i++) {
            float4 qv = *(const float4*)(baseq + i * 4);
            qv.x *= scale; qv.y *= scale; qv.z *= scale; qv.w *= scale;
            uint64_t h64, l64;
            split4h_64(qv, h64, l64);
            *(uint64_t*)&qh[n][c0 + i * 4] = h64;
            *(uint64_t*)&ql[n][c0 + i * 4] = l64;
        }
        // k: 16 halves = 2x uint4
        *(uint4*)&kh[n][c0]     = *(const uint4*)(basekv);
        *(uint4*)&kh[n][c0 + 8] = *(const uint4*)(basekv + 8);
        // v: 16 halves = 2x uint4
        *(uint4*)&vh[n][c0]     = *(const uint4*)(basekv + 192);
        *(uint4*)&vh[n][c0 + 8] = *(const uint4*)(basekv + 200);
    }
    __syncthreads();

    // ---- QK^T (2-pass fused) ----
    float s[8][4];
#pragma unroll
    for (int j = 0; j < 8; j++)
#pragma unroll
        for (int e = 0; e < 4; e++) s[j][e] = 0.0f;

    const uint32_t qhB = smem_u32(&qh[0][0]);
    const uint32_t qlB = smem_u32(&ql[0][0]);
    const uint32_t khB = smem_u32(&kh[0][0]);
    const uint32_t aoff = (uint32_t)((16 * w + (lane & 15)) * 40 + ((lane >> 4) << 3));
    const uint32_t boff = (uint32_t)(((lane & 7) + ((lane >> 4) << 3)) * 40
                                     + (((lane >> 3) & 1) << 3));

#pragma unroll
    for (int ks = 0; ks < 2; ks++) {
        uint32_t Ah[4], Al[4];
        ldsm4(qhB + (aoff + ks * 16) * 2, Ah);
        ldsm4(qlB + (aoff + ks * 16) * 2, Al);
#pragma unroll
        for (int nt = 0; nt < 4; nt++) {
            uint32_t B[4];
            ldsm4(khB + (boff + nt * 16 * 40 + ks * 16) * 2, B);
            mma16816(s[2 * nt],     Ah, B[0], B[1]);
            mma16816(s[2 * nt + 1], Ah, B[2], B[3]);
            mma16816(s[2 * nt],     Al, B[0], B[1]);
            mma16816(s[2 * nt + 1], Al, B[2], B[3]);
        }
    }

    // ---- bias + softmax (rows r0 = 16w + lane/4, r1 = r0+8) ----
    const int r0 = 16 * w + (lane >> 2);
    const int cb = 2 * (lane & 3);
    const float* bm = bmat + h * 4096;
#pragma unroll
    for (int j = 0; j < 8; j++) {
        float2 b0 = *(const float2*)(bm + r0 * 64 + 8 * j + cb);
        float2 b1 = *(const float2*)(bm + (r0 + 8) * 64 + 8 * j + cb);
        s[j][0] += b0.x; s[j][1] += b0.y;
        s[j][2] += b1.x; s[j][3] += b1.y;
    }

    float mx0 = -1e30f, mx1 = -1e30f;
#pragma unroll
    for (int j = 0; j < 8; j++) {
        mx0 = fmaxf(mx0, fmaxf(s[j][0], s[j][1]));
        mx1 = fmaxf(mx1, fmaxf(s[j][2], s[j][3]));
    }
    mx0 = fmaxf(mx0, __shfl_xor_sync(0xffffffffu, mx0, 1));
    mx0 = fmaxf(mx0, __shfl_xor_sync(0xffffffffu, mx0, 2));
    mx1 = fmaxf(mx1, __shfl_xor_sync(0xffffffffu, mx1, 1));
    mx1 = fmaxf(mx1, __shfl_xor_sync(0xffffffffu, mx1, 2));

    float sum0 = 0.0f, sum1 = 0.0f;
#pragma unroll
    for (int j = 0; j < 8; j++) {
        s[j][0] = __expf(s[j][0] - mx0); sum0 += s[j][0];
        s[j][1] = __expf(s[j][1] - mx0); sum0 += s[j][1];
        s[j][2] = __expf(s[j][2] - mx1); sum1 += s[j][2];
        s[j][3] = __expf(s[j][3] - mx1); sum1 += s[j][3];
    }
    sum0 += __shfl_xor_sync(0xffffffffu, sum0, 1);
    sum0 += __shfl_xor_sync(0xffffffffu, sum0, 2);
    sum1 += __shfl_xor_sync(0xffffffffu, sum1, 1);
    sum1 += __shfl_xor_sync(0xffffffffu, sum1, 2);
    const float inv0 = 1.0f / sum0;
    const float inv1 = 1.0f / sum1;

    // ---- P -> fp16 hi/lo A-fragments in registers ----
    uint32_t ph[4][4], pl[4][4];
#pragma unroll
    for (int ks = 0; ks < 4; ks++) {
        const int j0 = 2 * ks, j1 = 2 * ks + 1;
        float p[8] = { s[j0][0] * inv0, s[j0][1] * inv0,
                       s[j0][2] * inv1, s[j0][3] * inv1,
                       s[j1][0] * inv0, s[j1][1] * inv0,
                       s[j1][2] * inv1, s[j1][3] * inv1 };
        float hi[8], lo[8];
#pragma unroll
        for (int e = 0; e < 8; e++) {
            __half hh = __float2half_rn(p[e]);
            hi[e] = __half2float(hh);
            lo[e] = p[e] - hi[e];
        }
        ph[ks][0] = packh2(hi[0], hi[1]); pl[ks][0] = packh2(lo[0], lo[1]);
        ph[ks][1] = packh2(hi[2], hi[3]); pl[ks][1] = packh2(lo[2], lo[3]);
        ph[ks][2] = packh2(hi[4], hi[5]); pl[ks][2] = packh2(lo[4], lo[5]);
        ph[ks][3] = packh2(hi[6], hi[7]); pl[ks][3] = packh2(lo[6], lo[7]);
    }

    // ---- PV (2-pass fused): B-fragments via ldmatrix.trans ----
    float o[4][4];
#pragma unroll
    for (int j = 0; j < 4; j++)
#pragma unroll
        for (int e = 0; e < 4; e++) o[j][e] = 0.0f;

    const uint32_t vhB = smem_u32(&vh[0][0]);
    const uint32_t vtoff = (uint32_t)(((lane & 7) + (((lane >> 3) & 1) << 3)) * 40
                                      + ((lane >> 4) << 3));

#pragma unroll
    for (int ks = 0; ks < 4; ks++) {
        uint32_t B0[4], B1[4];
        ldsm4t(vhB + (vtoff + ks * 16 * 40) * 2, B0);        // d 0-15
        ldsm4t(vhB + (vtoff + ks * 16 * 40 + 16) * 2, B1);   // d 16-31
        mma16816(o[0], ph[ks], B0[0], B0[1]);
        mma16816(o[1], ph[ks], B0[2], B0[3]);
        mma16816(o[2], ph[ks], B1[0], B1[1]);
        mma16816(o[3], ph[ks], B1[2], B1[3]);
        mma16816(o[0], pl[ks], B0[0], B0[1]);
        mma16816(o[1], pl[ks], B0[2], B0[3]);
        mma16816(o[2], pl[ks], B1[0], B1[1]);
        mma16816(o[3], pl[ks], B1[2], B1[3]);
    }

    // ---- store ----
    float* op = out + (size_t)(b * 64) * CDIM + h * HDIM;
#pragma unroll
    for (int j = 0; j < 4; j++) {
        const int d = 8 * j + cb;
        *(float2*)(op + (size_t)r0 * CDIM + d)       = make_float2(o[j][0], o[j][1]);
        *(float2*)(op + (size_t)(r0 + 8) * CDIM + d) = make_float2(o[j][2], o[j][3]);
    }
}

// ---------------------------------------------------------------------------
// Positional conv branch: reads dense g_vr [MROWS x 192].
// ---------------------------------------------------------------------------
#define CONV_SMEM ((32 * 192 + 32 * 193) * 4)   // 49280 bytes

__global__ __launch_bounds__(192, 2) void conv_kernel(
    const float* __restrict__ vr, const float* __restrict__ dw_w,
    const float* __restrict__ dw_b, const float* __restrict__ pw_w,
    const float* __restrict__ pw_b, float* __restrict__ att)
{
    extern __shared__ float smf[];
    float* ptc  = smf;                  // [32][192] depthwise chunk
    float* pw_s = smf + 32 * 192;       // [32][193] pw_s[d][c]

    const int b = blockIdx.x;
    const int c = threadIdx.x;

    const float* src = vr + (size_t)b * 64 * 192;
    float in[64];
#pragma unroll
    for (int p = 0; p < 64; p++) in[p] = src[p * 192 + c];

    float w[25];
#pragma unroll
    for (int i = 0; i < 25; i++) w[i] = dw_w[c * 25 + i];
    const float db = dw_b[c];

#pragma unroll
    for (int i = 0; i < 32; i++) {
        int idx = i * 192 + c;
        int cc = idx >> 5, d = idx & 31;
        pw_s[d * 193 + cc] = pw_w[idx];
    }
    __syncthreads();

    float wv[32];
#pragma unroll
    for (int d = 0; d < 32; d++) wv[d] = pw_s[d * 193 + c];
    const float pb = pw_b[c];
    const int g32 = (c >> 5) << 5;
    float* dst = att + (size_t)b * 64 * CDIM;

#pragma unroll
    for (int ch = 0; ch < 2; ch++) {
        const int pbase = ch * 32;
#pragma unroll
        for (int pp = 0; pp < 32; pp++) {
            const int p = pbase + pp;
            const int y = p >> 3, x = p & 7;
            float a = db;
#pragma unroll
            for (int ky = 0; ky < 5; ky++) {
                const int yy = y + ky - 2;
                if (yy < 0 || yy > 7) continue;
#pragma unroll
                for (int kx = 0; kx < 5; kx++) {
                    const int xx = x + kx - 2;
                    if (xx < 0 || xx > 7) continue;
                    a += in[yy * 8 + xx] * w[ky * 5 + kx];
                }
            }
            ptc[pp * 192 + c] = a;
        }
        __syncthreads();

#pragma unroll
        for (int pp = 0; pp < 32; pp++) {
            const float4* pr = (const float4*)(ptc + pp * 192 + g32);
            float a = pb;
#pragma unroll
            for (int d4 = 0; d4 < 8; d4++) {
                float4 v = pr[d4];
                a += v.x * wv[d4 * 4 + 0] + v.y * wv[d4 * 4 + 1]
                   + v.z * wv[d4 * 4 + 2] + v.w * wv[d4 * 4 + 3];
            }
            dst[(pbase + pp) * 192 + c] += a;
        }
        if (ch == 0) __syncthreads();
    }
}

// ---------------------------------------------------------------------------
extern "C" void kernel_launch(void* const* d_in, const int* in_sizes, int n_in,
                              void* d_out, int out_size)
{
    const float* x      = (const float*)d_in[0];
    const float* wq     = (const float*)d_in[1];
    const float* bq     = (const float*)d_in[2];
    const float* wkv    = (const float*)d_in[3];
    const float* bkv    = (const float*)d_in[4];
    const float* rpb    = (const float*)d_in[5];
    const int*   relidx = (const int*)  d_in[6];
    const float* dw_w   = (const float*)d_in[7];
    const float* dw_b   = (const float*)d_in[8];
    const float* pw_w   = (const float*)d_in[9];
    const float* pw_b   = (const float*)d_in[10];
    const float* proj_w = (const float*)d_in[11];
    const float* proj_b = (const float*)d_in[12];
    float* out = (float*)d_out;

    float *q, *vr, *att, *biasc, *bmat;
    __half *kvh, *wh, *pwh;
    cudaGetSymbolAddress((void**)&q,    g_q);
    cudaGetSymbolAddress((void**)&kvh,  g_kv);
    cudaGetSymbolAddress((void**)&vr,   g_vr);
    cudaGetSymbolAddress((void**)&att,  g_att);
    cudaGetSymbolAddress((void**)&wh,   g_wh);
    cudaGetSymbolAddress((void**)&pwh,  g_pwh);
    cudaGetSymbolAddress((void**)&biasc, g_bias);
    cudaGetSymbolAddress((void**)&bmat, g_bmat);

    cudaFuncSetAttribute(gemm_tc_kernel<2, 0>,
                         cudaFuncAttributeMaxDynamicSharedMemorySize, GEMM_SMEM);
    cudaFuncSetAttribute(gemm_tc_kernel<1, 1>,
                         cudaFuncAttributeMaxDynamicSharedMemorySize, GEMM_SMEM);
    cudaFuncSetAttribute(conv_kernel,
                         cudaFuncAttributeMaxDynamicSharedMemorySize, CONV_SMEM);

    // 0) weight prep (fp16) + bias matrices
    prep_w_kernel<<<(768 * 192 + 192 * 192 + 255) / 256, 256>>>(
        wq, wkv, bq, bkv, proj_w, rpb, relidx);

    // 1a) q GEMM: 2-pass, fp32 out -> g_q
    gemm_tc_kernel<2, 0><<<dim3(3, MROWS / 64), 128, GEMM_SMEM>>>(
        x, wh, biasc, q, 192);
    // 1b) k|v GEMM: 1-pass, fp16 out -> g_kv (attn truncates to fp16 anyway)
    gemm_tc_kernel<1, 1><<<dim3(6, MROWS / 64), 128, GEMM_SMEM>>>(
        x, wh + 192 * 192, biasc + 192, kvh, 384);
    // 1c) v_r GEMM: 2-pass, fp32 out -> g_vr (conv needs precision)
    gemm_tc_kernel<2, 0><<<dim3(3, MROWS / 64), 128, GEMM_SMEM>>>(
        x, wh + 576 * 192, biasc + 576, vr, 192);

    // 2) attention -> g_att
    attn_kernel<<<BATCH * NHEAD, 128>>>(q, kvh, bmat, att);

    // 3) conv branch accumulates into g_att
    conv_kernel<<<BATCH, 192, CONV_SMEM>>>(vr, dw_w, dw_b, pw_w, pw_b, att);

    // 4) proj GEMM -> d_out
    gemm_tc_kernel<2, 0><<<dim3(3, MROWS / 64), 128, GEMM_SMEM>>>(
        att, pwh, proj_b, out, 192);
}